// round 13
// baseline (speedup 1.0000x reference)
#include <cuda_runtime.h>
#include <cuda_bf16.h>
#include <cstdint>
#include <cstddef>

#define HH 128
#define WW 128
#define HW 16384
#define CC 192
#define C3 576
#define BB 8
#define NHEADS 4
#define CH 48
#define GK 192

// gemm tiling
#define AS_HALF (64 * 200)          // A smem elems per half (64 rows, 192+8 pad)
#define BS_HALF (32 * 136)          // B smem elems per half per buf (32 rows, 128+8 pad)
#define BS_BUF  (2 * BS_HALF)
#define GEMM_SMEM ((2 * AS_HALF + 2 * BS_BUF) * 2)   // 86016 bytes

// ---------------- scratch (static device globals) ----------------
__device__ float g_mask[BB * HW];
__device__ float g_qkv [(size_t)BB * C3 * HW];
__device__ float g_qkvd[(size_t)BB * 2 * CC * HW];   // only q,k kept in f32
__device__ float g_ssp [BB * 2 * CC * 32];
__device__ float g_sumsq[BB * 2 * CC];
__device__ float g_Spart[(size_t)32 * BB * NHEADS * CH * CH];
__device__ __nv_bfloat16 g_Whi[C3 * GK];
__device__ __nv_bfloat16 g_Wlo[C3 * GK];
__device__ __nv_bfloat16 g_xhi[(size_t)BB * GK * HW];
__device__ __nv_bfloat16 g_xlo[(size_t)BB * GK * HW];
__device__ __nv_bfloat16 g_vhi[(size_t)BB * GK * HW];
__device__ __nv_bfloat16 g_vlo[(size_t)BB * GK * HW];
__device__ __nv_bfloat16 g_Mhi[BB * CC * CC];
__device__ __nv_bfloat16 g_Mlo[BB * CC * CC];

// ---------------- helpers ----------------
__device__ __forceinline__ unsigned long long fma2(unsigned long long a,
                                                   unsigned long long b,
                                                   unsigned long long c) {
    unsigned long long d;
    asm("fma.rn.f32x2 %0, %1, %2, %3;" : "=l"(d) : "l"(a), "l"(b), "l"(c));
    return d;
}
__device__ __forceinline__ float2 unpack2(unsigned long long v) {
    float2 r;
    asm("mov.b64 {%0, %1}, %2;" : "=f"(r.x), "=f"(r.y) : "l"(v));
    return r;
}
__device__ __forceinline__ uint32_t smem_u32(const void* p) {
    uint32_t a;
    asm("{ .reg .u64 t; cvta.to.shared.u64 t, %1; cvt.u32.u64 %0, t; }"
        : "=r"(a) : "l"(p));
    return a;
}
__device__ __forceinline__ void cp16(uint32_t dst, const void* src) {
    asm volatile("cp.async.cg.shared.global [%0], [%1], 16;"
                 :: "r"(dst), "l"(src));
}
__device__ __forceinline__ void ldsm4(uint32_t* r, uint32_t a) {
    asm volatile("ldmatrix.sync.aligned.m8n8.x4.shared.b16 {%0,%1,%2,%3}, [%4];"
        : "=r"(r[0]), "=r"(r[1]), "=r"(r[2]), "=r"(r[3]) : "r"(a));
}
__device__ __forceinline__ void ldsm4t(uint32_t* r, uint32_t a) {
    asm volatile("ldmatrix.sync.aligned.m8n8.x4.trans.shared.b16 {%0,%1,%2,%3}, [%4];"
        : "=r"(r[0]), "=r"(r[1]), "=r"(r[2]), "=r"(r[3]) : "r"(a));
}
__device__ __forceinline__ void mma16816(float* c, const uint32_t* a,
                                         const uint32_t* b) {
    asm volatile(
        "mma.sync.aligned.m16n8k16.row.col.f32.bf16.bf16.f32 "
        "{%0,%1,%2,%3}, {%4,%5,%6,%7}, {%8,%9}, {%0,%1,%2,%3};"
        : "+f"(c[0]), "+f"(c[1]), "+f"(c[2]), "+f"(c[3])
        : "r"(a[0]), "r"(a[1]), "r"(a[2]), "r"(a[3]), "r"(b[0]), "r"(b[1]));
}

// ---------------- K1: mask ----------------
__global__ void __launch_bounds__(256) mask_kernel(
    const float* __restrict__ x, const float* __restrict__ inp,
    const float* __restrict__ cmw, const float* __restrict__ thr_p,
    float* __restrict__ mask)
{
    __shared__ float cw[CC];
    int t = threadIdx.x;
    if (t < CC) cw[t] = cmw[t];
    __syncthreads();
    float thr = *thr_p;
    int p = blockIdx.x * 256 + t;
    int b = blockIdx.y;
    size_t off = (size_t)b * CC * HW + p;
    float acc = 0.f;
#pragma unroll 4
    for (int c = 0; c < CC; c++) {
        float d = inp[off + (size_t)c * HW] - x[off + (size_t)c * HW];
        acc += (d > thr) ? cw[c] : 0.f;
    }
    mask[(size_t)b * HW + p] = acc;
}

// ---------------- convert W [576][192] f32 -> bf16 hi/lo ----------------
__global__ void __launch_bounds__(192) convw_kernel(
    const float* __restrict__ W, __nv_bfloat16* __restrict__ whi,
    __nv_bfloat16* __restrict__ wlo)
{
    int i = blockIdx.x * 192 + threadIdx.x;
    float v = W[i];
    __nv_bfloat16 h = __float2bfloat16(v);
    whi[i] = h;
    wlo[i] = __float2bfloat16(v - __bfloat162float(h));
}

// ------- convert B [192][16384] f32 -> bf16 hi/lo, same layout (8 elems/thread) -----
__global__ void __launch_bounds__(256) convb_kernel(
    const float* __restrict__ in, size_t sIn,
    __nv_bfloat16* __restrict__ ohi, __nv_bfloat16* __restrict__ olo)
{
    size_t e0 = ((size_t)blockIdx.x * 256 + threadIdx.x) * 8;
    int b = blockIdx.y;
    const float4* src = (const float4*)(in + (size_t)b * sIn + e0);
    float4 v0 = src[0], v1 = src[1];
    float vv[8] = {v0.x, v0.y, v0.z, v0.w, v1.x, v1.y, v1.z, v1.w};
    __nv_bfloat16 hb[8], lb[8];
#pragma unroll
    for (int i = 0; i < 8; i++) {
        hb[i] = __float2bfloat16(vv[i]);
        lb[i] = __float2bfloat16(vv[i] - __bfloat162float(hb[i]));
    }
    size_t o = (size_t)b * GK * HW + e0;
    *(uint4*)(ohi + o) = *(const uint4*)hb;
    *(uint4*)(olo + o) = *(const uint4*)lb;
}

// ------------- HMMA bf16-split GEMM: C[M,16384] = A[M,192] @ B[192,16384] -----------
// CTA: M=64, N=128, 8 warps (warp tile 32x32). A resident; B double-buffered k32.
// 3 passes hi*hi + hi*lo + lo*hi fused in the k-loop.
__global__ void __launch_bounds__(256) gemm_hmma(
    const __nv_bfloat16* __restrict__ Ahi, const __nv_bfloat16* __restrict__ Alo,
    size_t sA,
    const __nv_bfloat16* __restrict__ Bhi, const __nv_bfloat16* __restrict__ Blo,
    size_t sB, float* __restrict__ C, size_t sC)
{
    extern __shared__ __nv_bfloat16 sm[];
    __nv_bfloat16* As = sm;                    // [2 half][64][200]
    __nv_bfloat16* Bs = sm + 2 * AS_HALF;      // [2 buf][2 half][32][136]
    const int N = HW;
    int b = blockIdx.z;
    Ahi += (size_t)b * sA; Alo += (size_t)b * sA;
    Bhi += (size_t)b * sB; Blo += (size_t)b * sB;
    C   += (size_t)b * sC;
    int n0 = blockIdx.x * 128, m0 = blockIdx.y * 64;
    int tid = threadIdx.x, lane = tid & 31, w = tid >> 5;
    int wm = (w & 1) * 32;          // 2 warps along M
    int wn = (w >> 1) * 32;         // 4 warps along N
    uint32_t sAu = smem_u32(As), sBu = smem_u32(Bs);

    // ---- prefetch B chunk 0 (group 0) ----
#pragma unroll
    for (int i = 0; i < 4; i++) {
        int idx = tid + i * 256;               // 0..1023
        int half = idx >> 9, r = (idx >> 4) & 31, seg = idx & 15;
        const __nv_bfloat16* src =
            (half ? Blo : Bhi) + (size_t)r * N + n0 + seg * 8;
        cp16(sBu + 2 * (half * BS_HALF + r * 136 + seg * 8), src);
    }
    asm volatile("cp.async.commit_group;" ::: "memory");
    // ---- stage A (group 1) ----
#pragma unroll
    for (int i = 0; i < 12; i++) {
        int idx = tid + i * 256;               // 0..3071
        int half = idx >= 1536;
        int r = (idx - half * 1536) / 24;
        int seg = idx % 24;
        const __nv_bfloat16* src =
            (half ? Alo : Ahi) + (size_t)(m0 + r) * GK + seg * 8;
        cp16(sAu + 2 * (half * AS_HALF + r * 200 + seg * 8), src);
    }
    asm volatile("cp.async.commit_group;" ::: "memory");

    float acc[2][4][4];
#pragma unroll
    for (int i = 0; i < 2; i++)
#pragma unroll
        for (int j = 0; j < 4; j++)
#pragma unroll
            for (int q = 0; q < 4; q++) acc[i][j][q] = 0.f;

    int a_lr = (lane & 15), a_kh = (lane >> 4) << 3;

    for (int kt = 0; kt < 6; kt++) {
        int buf = kt & 1;
        if (kt < 5) {
#pragma unroll
            for (int i = 0; i < 4; i++) {
                int idx = tid + i * 256;
                int half = idx >> 9, r = (idx >> 4) & 31, seg = idx & 15;
                const __nv_bfloat16* src = (half ? Blo : Bhi)
                    + (size_t)((kt + 1) * 32 + r) * N + n0 + seg * 8;
                cp16(sBu + 2 * ((buf ^ 1) * BS_BUF + half * BS_HALF
                                + r * 136 + seg * 8), src);
            }
            asm volatile("cp.async.commit_group;" ::: "memory");
            asm volatile("cp.async.wait_group 1;" ::: "memory");
        } else {
            asm volatile("cp.async.wait_group 0;" ::: "memory");
        }
        __syncthreads();
#pragma unroll
        for (int ks = 0; ks < 2; ks++) {
            int k0 = kt * 32 + ks * 16;
            uint32_t Ah[2][4], Al[2][4], Bh[2][4], Bl[2][4];
#pragma unroll
            for (int mt = 0; mt < 2; mt++) {
                uint32_t addr = sAu + 2 * ((wm + mt * 16 + a_lr) * 200 + k0 + a_kh);
                ldsm4(Ah[mt], addr);
                ldsm4(Al[mt], addr + 2 * AS_HALF);
            }
#pragma unroll
            for (int j = 0; j < 2; j++) {
                uint32_t addr = sBu + 2 * (buf * BS_BUF
                    + (ks * 16 + a_lr) * 136 + wn + j * 16 + a_kh);
                ldsm4t(Bh[j], addr);
                ldsm4t(Bl[j], addr + 2 * BS_HALF);
            }
#pragma unroll
            for (int mt = 0; mt < 2; mt++)
#pragma unroll
                for (int j = 0; j < 2; j++)
#pragma unroll
                    for (int hn = 0; hn < 2; hn++) {
                        float* c = acc[mt][j * 2 + hn];
                        mma16816(c, Ah[mt], &Bh[j][hn * 2]);
                        mma16816(c, Ah[mt], &Bl[j][hn * 2]);
                        mma16816(c, Al[mt], &Bh[j][hn * 2]);
                    }
        }
        __syncthreads();
    }

    int g = lane >> 2, tg = lane & 3;
#pragma unroll
    for (int mt = 0; mt < 2; mt++) {
        int row = m0 + wm + mt * 16 + g;
#pragma unroll
        for (int nt = 0; nt < 4; nt++) {
            int col = n0 + wn + nt * 8 + tg * 2;
            float* c = acc[mt][nt];
            *(float2*)&C[(size_t)row * N + col]       = make_float2(c[0], c[1]);
            *(float2*)&C[(size_t)(row + 8) * N + col] = make_float2(c[2], c[3]);
        }
    }
}

// ------- K3: depthwise 3x3, 4 rows/thread; q,k -> f32(+mask+sumsq), v -> bf16 -------
__global__ void __launch_bounds__(128) dw_kernel(
    const float* __restrict__ in, const float* __restrict__ dww,
    const float* __restrict__ mask, float* __restrict__ out,
    float* __restrict__ ssp,
    __nv_bfloat16* __restrict__ vhi, __nv_bfloat16* __restrict__ vlo)
{
    int xx = threadIdx.x;
    int y0 = blockIdx.x * 4;
    int oc = blockIdx.y, b = blockIdx.z;
    size_t base = ((size_t)b * C3 + oc) * HW;
    float w[9];
#pragma unroll
    for (int i = 0; i < 9; i++) w[i] = __ldg(&dww[oc * 9 + i]);
    float cl[6], cm[6], cr[6];
#pragma unroll
    for (int i = 0; i < 6; i++) {
        int yy = y0 - 1 + i;
        bool vy = (yy >= 0) && (yy < HH);
        const float* rp = in + base + (size_t)yy * WW;
        cm[i] = vy ? rp[xx] : 0.f;
        cl[i] = (vy && xx > 0)      ? rp[xx - 1] : 0.f;
        cr[i] = (vy && xx < WW - 1) ? rp[xx + 1] : 0.f;
    }
    float acc[4];
#pragma unroll
    for (int r = 0; r < 4; r++) {
        float a = 0.f;
#pragma unroll
        for (int j = 0; j < 3; j++)
            a += cl[r+j]*w[j*3] + cm[r+j]*w[j*3+1] + cr[r+j]*w[j*3+2];
        acc[r] = a;
    }
    if (oc < 2 * CC) {          // q or k: apply mask, f32 out, sumsq partials
        float ss = 0.f;
#pragma unroll
        for (int r = 0; r < 4; r++) {
            float mv = mask[(size_t)b * HW + (y0 + r) * WW + xx];
            acc[r] *= mv;
            ss += acc[r] * acc[r];
        }
#pragma unroll
        for (int o = 16; o; o >>= 1) ss += __shfl_down_sync(0xffffffffu, ss, o);
        __shared__ float red[4];
        if ((xx & 31) == 0) red[xx >> 5] = ss;
        __syncthreads();
        if (xx == 0)
            ssp[(size_t)(b * 2 * CC + oc) * 32 + blockIdx.x] =
                red[0] + red[1] + red[2] + red[3];
        size_t ob = ((size_t)b * 2 * CC + oc) * HW;
#pragma unroll
        for (int r = 0; r < 4; r++)
            out[ob + (size_t)(y0 + r) * WW + xx] = acc[r];
    } else {                    // v: write split bf16 directly
        size_t vb = ((size_t)b * GK + (oc - 2 * CC)) * HW;
#pragma unroll
        for (int r = 0; r < 4; r++) {
            __nv_bfloat16 h = __float2bfloat16(acc[r]);
            vhi[vb + (size_t)(y0 + r) * WW + xx] = h;
            vlo[vb + (size_t)(y0 + r) * WW + xx] =
                __float2bfloat16(acc[r] - __bfloat162float(h));
        }
    }
}

// ---------------- K3b: sumsq reduce ----------------
__global__ void __launch_bounds__(32) ssreduce_kernel(
    const float* __restrict__ part, float* __restrict__ sumsq)
{
    int id = blockIdx.x, t = threadIdx.x;
    float v = part[(size_t)id * 32 + t];
#pragma unroll
    for (int o = 16; o; o >>= 1) v += __shfl_down_sync(0xffffffffu, v, o);
    if (t == 0) sumsq[id] = v;
}

// ---------------- K4: QK^T partials (f32x2) ----------------
__global__ void __launch_bounds__(64) qk_kernel(
    const float* __restrict__ qk, float* __restrict__ Spart)
{
    int chunk = blockIdx.x, h = blockIdx.y, b = blockIdx.z;
    const float* qbase = qk + ((size_t)b * 2 * CC + h * CH) * HW;
    const float* kbase = qk + ((size_t)b * 2 * CC + CC + h * CH) * HW;
    int p0 = chunk * 512;
    __shared__ float qs[CH][34];
    __shared__ float ks[CH][34];
    int t = threadIdx.x, ti = t >> 3, tj = t & 7;
    unsigned long long acc[6][6];
#pragma unroll
    for (int i = 0; i < 6; i++)
#pragma unroll
        for (int j = 0; j < 6; j++) acc[i][j] = 0ULL;
    for (int sub = 0; sub < 16; sub++) {
        int pp = p0 + sub * 32;
        __syncthreads();
#pragma unroll
        for (int j = 0; j < 6; j++) {
            int id = t + j * 64;
            int row = id >> 3, c4 = (id & 7) * 4;
            float4 v = *(const float4*)(qbase + (size_t)row * HW + pp + c4);
            qs[row][c4] = v.x; qs[row][c4+1] = v.y;
            qs[row][c4+2] = v.z; qs[row][c4+3] = v.w;
            float4 w = *(const float4*)(kbase + (size_t)row * HW + pp + c4);
            ks[row][c4] = w.x; ks[row][c4+1] = w.y;
            ks[row][c4+2] = w.z; ks[row][c4+3] = w.w;
        }
        __syncthreads();
#pragma unroll
        for (int kk = 0; kk < 16; kk++) {
            unsigned long long q2[6], k2[6];
#pragma unroll
            for (int i = 0; i < 6; i++)
                q2[i] = *(const unsigned long long*)&qs[ti * 6 + i][kk * 2];
#pragma unroll
            for (int j = 0; j < 6; j++)
                k2[j] = *(const unsigned long long*)&ks[tj * 6 + j][kk * 2];
#pragma unroll
            for (int i = 0; i < 6; i++)
#pragma unroll
                for (int j = 0; j < 6; j++)
                    acc[i][j] = fma2(q2[i], k2[j], acc[i][j]);
        }
    }
    float* Sp = Spart + (size_t)chunk * (BB * NHEADS * CH * CH)
                      + (size_t)(b * NHEADS + h) * (CH * CH);
#pragma unroll
    for (int i = 0; i < 6; i++)
#pragma unroll
        for (int j = 0; j < 6; j++) {
            float2 f = unpack2(acc[i][j]);
            Sp[(ti * 6 + i) * CH + tj * 6 + j] = f.x + f.y;
        }
}

// ------ K5: reduce S + cosine scale + softmax + fold proj -> M (bf16 hi/lo) --------
__global__ void __launch_bounds__(256) attn_kernel(
    const float* __restrict__ Spart, const float* __restrict__ sumsq,
    const float* __restrict__ temp, const float* __restrict__ projw,
    __nv_bfloat16* __restrict__ Mhi, __nv_bfloat16* __restrict__ Mlo)
{
    int h = blockIdx.x, b = blockIdx.y;
    __shared__ float att[CH][CH];
    __shared__ float rnq[CH], rnk[CH];
    int t = threadIdx.x;
    if (t < CH) {
        float nq = sqrtf(sumsq[b * 2 * CC + h * CH + t]);
        float nk = sqrtf(sumsq[b * 2 * CC + CC + h * CH + t]);
        rnq[t] = 1.f / fmaxf(nq, 1e-12f);
        rnk[t] = 1.f / fmaxf(nk, 1e-12f);
    }
    __syncthreads();
    float T = temp[h];
    size_t sp0 = (size_t)(b * NHEADS + h) * (CH * CH);
    for (int i = t; i < CH * CH; i += 256) {
        float s = 0.f;
#pragma unroll
        for (int c = 0; c < 32; c++)
            s += Spart[(size_t)c * (BB * NHEADS * CH * CH) + sp0 + i];
        int cR = i / CH, d = i % CH;
        att[cR][d] = s * rnq[cR] * rnk[d] * T;
    }
    __syncthreads();
    if (t < CH) {
        float mx = -1e30f;
#pragma unroll
        for (int d = 0; d < CH; d++) mx = fmaxf(mx, att[t][d]);
        float sum = 0.f;
#pragma unroll
        for (int d = 0; d < CH; d++) {
            float e = expf(att[t][d] - mx);
            att[t][d] = e;
            sum += e;
        }
        float inv = 1.f / sum;
#pragma unroll
        for (int d = 0; d < CH; d++) att[t][d] *= inv;
    }
    __syncthreads();
    for (int i = t; i < CC * CH; i += 256) {
        int o = i / CH, d = i % CH;
        float s = 0.f;
#pragma unroll
        for (int c = 0; c < CH; c++)
            s += projw[o * CC + h * CH + c] * att[c][d];
        size_t idx = ((size_t)b * CC + o) * CC + h * CH + d;
        __nv_bfloat16 hi = __float2bfloat16(s);
        Mhi[idx] = hi;
        Mlo[idx] = __float2bfloat16(s - __bfloat162float(hi));
    }
}

// ---------------- launch ----------------
extern "C" void kernel_launch(void* const* d_in, const int* in_sizes, int n_in,
                              void* d_out, int out_size)
{
    const float* x     = (const float*)d_in[0];
    const float* inp   = (const float*)d_in[1];
    const float* qkvw  = (const float*)d_in[2];
    const float* dww   = (const float*)d_in[3];
    const float* projw = (const float*)d_in[4];
    const float* cmw   = (const float*)d_in[5];
    const float* temp  = (const float*)d_in[6];
    const float* thr   = (const float*)d_in[7];
    float* out = (float*)d_out;

    float *p_mask, *p_qkv, *p_qkvd, *p_ssp, *p_sumsq, *p_spart;
    __nv_bfloat16 *p_whi, *p_wlo, *p_xhi, *p_xlo, *p_vhi, *p_vlo, *p_mhi, *p_mlo;
    cudaGetSymbolAddress((void**)&p_mask,  g_mask);
    cudaGetSymbolAddress((void**)&p_qkv,   g_qkv);
    cudaGetSymbolAddress((void**)&p_qkvd,  g_qkvd);
    cudaGetSymbolAddress((void**)&p_ssp,   g_ssp);
    cudaGetSymbolAddress((void**)&p_sumsq, g_sumsq);
    cudaGetSymbolAddress((void**)&p_spart, g_Spart);
    cudaGetSymbolAddress((void**)&p_whi,   g_Whi);
    cudaGetSymbolAddress((void**)&p_wlo,   g_Wlo);
    cudaGetSymbolAddress((void**)&p_xhi,   g_xhi);
    cudaGetSymbolAddress((void**)&p_xlo,   g_xlo);
    cudaGetSymbolAddress((void**)&p_vhi,   g_vhi);
    cudaGetSymbolAddress((void**)&p_vlo,   g_vlo);
    cudaGetSymbolAddress((void**)&p_mhi,   g_Mhi);
    cudaGetSymbolAddress((void**)&p_mlo,   g_Mlo);

    cudaFuncSetAttribute(gemm_hmma,
        cudaFuncAttributeMaxDynamicSharedMemorySize, GEMM_SMEM);

    // K1: mask
    mask_kernel<<<dim3(HW / 256, BB), 256>>>(x, inp, cmw, thr, p_mask);
    // converts for K2
    convw_kernel<<<C3, 192>>>(qkvw, p_whi, p_wlo);
    convb_kernel<<<dim3(GK * HW / (256 * 8), BB), 256>>>(
        x, (size_t)CC * HW, p_xhi, p_xlo);
    // K2: qkv = W @ x  (tensor cores, bf16 split x3)
    gemm_hmma<<<dim3(HW / 128, C3 / 64, BB), 256, GEMM_SMEM>>>(
        p_whi, p_wlo, (size_t)0, p_xhi, p_xlo, (size_t)GK * HW,
        p_qkv, (size_t)C3 * HW);
    // K3: depthwise 3x3; q,k -> f32 + mask + sumsq; v -> bf16 hi/lo
    dw_kernel<<<dim3(HH / 4, C3, BB), 128>>>(p_qkv, dww, p_mask, p_qkvd, p_ssp,
                                             p_vhi, p_vlo);
    ssreduce_kernel<<<BB * 2 * CC, 32>>>(p_ssp, p_sumsq);
    // K4: S partials
    qk_kernel<<<dim3(32, NHEADS, BB), 64>>>(p_qkvd, p_spart);
    // K5: softmax + fold proj -> bf16 hi/lo M
    attn_kernel<<<dim3(NHEADS, BB), 256>>>(p_spart, p_sumsq, temp, projw,
                                           p_mhi, p_mlo);
    // K6: out = M @ v  (tensor cores)
    gemm_hmma<<<dim3(HW / 128, CC / 64, BB), 256, GEMM_SMEM>>>(
        p_mhi, p_mlo, (size_t)CC * CC, p_vhi, p_vlo, (size_t)GK * HW,
        out, (size_t)CC * HW);
}

// round 14
// speedup vs baseline: 1.0001x; 1.0001x over previous
#include <cuda_runtime.h>
#include <cuda_bf16.h>
#include <cstdint>
#include <cstddef>

#define HH 128
#define WW 128
#define HW 16384
#define CC 192
#define C3 576
#define BB 8
#define NHEADS 4
#define CH 48
#define GK 192

// gemm tiling
#define AS_HALF (64 * 200)          // A smem elems per half (64 rows, 192+8 pad)
#define BS_HALF (32 * 136)          // B smem elems per half per buf (32 rows, 128+8 pad)
#define BS_BUF  (2 * BS_HALF)
#define GEMM_SMEM ((2 * AS_HALF + 2 * BS_BUF) * 2)   // 86016 bytes

// ---------------- scratch (static device globals) ----------------
__device__ float g_mask[BB * HW];
__device__ float g_qkv [(size_t)BB * C3 * HW];
__device__ float g_qkvd[(size_t)BB * 2 * CC * HW];   // only q,k kept in f32
__device__ float g_ssp [BB * 2 * CC * 32];
__device__ float g_sumsq[BB * 2 * CC];
__device__ float g_Spart[(size_t)32 * BB * NHEADS * CH * CH];
__device__ __nv_bfloat16 g_Whi[C3 * GK];
__device__ __nv_bfloat16 g_Wlo[C3 * GK];
__device__ __nv_bfloat16 g_xhi[(size_t)BB * GK * HW];
__device__ __nv_bfloat16 g_xlo[(size_t)BB * GK * HW];
__device__ __nv_bfloat16 g_vhi[(size_t)BB * GK * HW];
__device__ __nv_bfloat16 g_vlo[(size_t)BB * GK * HW];
__device__ __nv_bfloat16 g_Mhi[BB * CC * CC];
__device__ __nv_bfloat16 g_Mlo[BB * CC * CC];

// ---------------- helpers ----------------
__device__ __forceinline__ unsigned long long fma2(unsigned long long a,
                                                   unsigned long long b,
                                                   unsigned long long c) {
    unsigned long long d;
    asm("fma.rn.f32x2 %0, %1, %2, %3;" : "=l"(d) : "l"(a), "l"(b), "l"(c));
    return d;
}
__device__ __forceinline__ float2 unpack2(unsigned long long v) {
    float2 r;
    asm("mov.b64 {%0, %1}, %2;" : "=f"(r.x), "=f"(r.y) : "l"(v));
    return r;
}
__device__ __forceinline__ uint32_t smem_u32(const void* p) {
    uint32_t a;
    asm("{ .reg .u64 t; cvta.to.shared.u64 t, %1; cvt.u32.u64 %0, t; }"
        : "=r"(a) : "l"(p));
    return a;
}
__device__ __forceinline__ void cp16(uint32_t dst, const void* src) {
    asm volatile("cp.async.cg.shared.global [%0], [%1], 16;"
                 :: "r"(dst), "l"(src));
}
__device__ __forceinline__ void ldsm4(uint32_t* r, uint32_t a) {
    asm volatile("ldmatrix.sync.aligned.m8n8.x4.shared.b16 {%0,%1,%2,%3}, [%4];"
        : "=r"(r[0]), "=r"(r[1]), "=r"(r[2]), "=r"(r[3]) : "r"(a));
}
__device__ __forceinline__ void ldsm4t(uint32_t* r, uint32_t a) {
    asm volatile("ldmatrix.sync.aligned.m8n8.x4.trans.shared.b16 {%0,%1,%2,%3}, [%4];"
        : "=r"(r[0]), "=r"(r[1]), "=r"(r[2]), "=r"(r[3]) : "r"(a));
}
__device__ __forceinline__ void mma16816(float* c, const uint32_t* a,
                                         const uint32_t* b) {
    asm volatile(
        "mma.sync.aligned.m16n8k16.row.col.f32.bf16.bf16.f32 "
        "{%0,%1,%2,%3}, {%4,%5,%6,%7}, {%8,%9}, {%0,%1,%2,%3};"
        : "+f"(c[0]), "+f"(c[1]), "+f"(c[2]), "+f"(c[3])
        : "r"(a[0]), "r"(a[1]), "r"(a[2]), "r"(a[3]), "r"(b[0]), "r"(b[1]));
}

// ---------------- K1: mask ----------------
__global__ void __launch_bounds__(256) mask_kernel(
    const float* __restrict__ x, const float* __restrict__ inp,
    const float* __restrict__ cmw, const float* __restrict__ thr_p,
    float* __restrict__ mask)
{
    __shared__ float cw[CC];
    int t = threadIdx.x;
    if (t < CC) cw[t] = cmw[t];
    __syncthreads();
    float thr = *thr_p;
    int p = blockIdx.x * 256 + t;
    int b = blockIdx.y;
    size_t off = (size_t)b * CC * HW + p;
    float acc = 0.f;
#pragma unroll 4
    for (int c = 0; c < CC; c++) {
        float d = inp[off + (size_t)c * HW] - x[off + (size_t)c * HW];
        acc += (d > thr) ? cw[c] : 0.f;
    }
    mask[(size_t)b * HW + p] = acc;
}

// ---------------- convert W [576][192] f32 -> bf16 hi/lo ----------------
__global__ void __launch_bounds__(192) convw_kernel(
    const float* __restrict__ W, __nv_bfloat16* __restrict__ whi,
    __nv_bfloat16* __restrict__ wlo)
{
    int i = blockIdx.x * 192 + threadIdx.x;
    float v = W[i];
    __nv_bfloat16 h = __float2bfloat16(v);
    whi[i] = h;
    wlo[i] = __float2bfloat16(v - __bfloat162float(h));
}

// ------- convert B [192][16384] f32 -> bf16 hi/lo, same layout (8 elems/thread) -----
__global__ void __launch_bounds__(256) convb_kernel(
    const float* __restrict__ in, size_t sIn,
    __nv_bfloat16* __restrict__ ohi, __nv_bfloat16* __restrict__ olo)
{
    size_t e0 = ((size_t)blockIdx.x * 256 + threadIdx.x) * 8;
    int b = blockIdx.y;
    const float4* src = (const float4*)(in + (size_t)b * sIn + e0);
    float4 v0 = src[0], v1 = src[1];
    float vv[8] = {v0.x, v0.y, v0.z, v0.w, v1.x, v1.y, v1.z, v1.w};
    __nv_bfloat16 hb[8], lb[8];
#pragma unroll
    for (int i = 0; i < 8; i++) {
        hb[i] = __float2bfloat16(vv[i]);
        lb[i] = __float2bfloat16(vv[i] - __bfloat162float(hb[i]));
    }
    size_t o = (size_t)b * GK * HW + e0;
    *(uint4*)(ohi + o) = *(const uint4*)hb;
    *(uint4*)(olo + o) = *(const uint4*)lb;
}

// ------------- HMMA bf16-split GEMM: C[M,16384] = A[M,192] @ B[192,16384] -----------
// CTA: M=64, N=128, 8 warps (warp tile 32x32). A resident; B double-buffered k32.
// 3 passes hi*hi + hi*lo + lo*hi fused in the k-loop.
__global__ void __launch_bounds__(256) gemm_hmma(
    const __nv_bfloat16* __restrict__ Ahi, const __nv_bfloat16* __restrict__ Alo,
    size_t sA,
    const __nv_bfloat16* __restrict__ Bhi, const __nv_bfloat16* __restrict__ Blo,
    size_t sB, float* __restrict__ C, size_t sC)
{
    extern __shared__ __nv_bfloat16 sm[];
    __nv_bfloat16* As = sm;                    // [2 half][64][200]
    __nv_bfloat16* Bs = sm + 2 * AS_HALF;      // [2 buf][2 half][32][136]
    const int N = HW;
    int b = blockIdx.z;
    Ahi += (size_t)b * sA; Alo += (size_t)b * sA;
    Bhi += (size_t)b * sB; Blo += (size_t)b * sB;
    C   += (size_t)b * sC;
    int n0 = blockIdx.x * 128, m0 = blockIdx.y * 64;
    int tid = threadIdx.x, lane = tid & 31, w = tid >> 5;
    int wm = (w & 1) * 32;          // 2 warps along M
    int wn = (w >> 1) * 32;         // 4 warps along N
    uint32_t sAu = smem_u32(As), sBu = smem_u32(Bs);

    // ---- prefetch B chunk 0 (group 0) ----
#pragma unroll
    for (int i = 0; i < 4; i++) {
        int idx = tid + i * 256;               // 0..1023
        int half = idx >> 9, r = (idx >> 4) & 31, seg = idx & 15;
        const __nv_bfloat16* src =
            (half ? Blo : Bhi) + (size_t)r * N + n0 + seg * 8;
        cp16(sBu + 2 * (half * BS_HALF + r * 136 + seg * 8), src);
    }
    asm volatile("cp.async.commit_group;" ::: "memory");
    // ---- stage A (group 1) ----
#pragma unroll
    for (int i = 0; i < 12; i++) {
        int idx = tid + i * 256;               // 0..3071
        int half = idx >= 1536;
        int r = (idx - half * 1536) / 24;
        int seg = idx % 24;
        const __nv_bfloat16* src =
            (half ? Alo : Ahi) + (size_t)(m0 + r) * GK + seg * 8;
        cp16(sAu + 2 * (half * AS_HALF + r * 200 + seg * 8), src);
    }
    asm volatile("cp.async.commit_group;" ::: "memory");

    float acc[2][4][4];
#pragma unroll
    for (int i = 0; i < 2; i++)
#pragma unroll
        for (int j = 0; j < 4; j++)
#pragma unroll
            for (int q = 0; q < 4; q++) acc[i][j][q] = 0.f;

    int a_lr = (lane & 15), a_kh = (lane >> 4) << 3;

    for (int kt = 0; kt < 6; kt++) {
        int buf = kt & 1;
        if (kt < 5) {
#pragma unroll
            for (int i = 0; i < 4; i++) {
                int idx = tid + i * 256;
                int half = idx >> 9, r = (idx >> 4) & 31, seg = idx & 15;
                const __nv_bfloat16* src = (half ? Blo : Bhi)
                    + (size_t)((kt + 1) * 32 + r) * N + n0 + seg * 8;
                cp16(sBu + 2 * ((buf ^ 1) * BS_BUF + half * BS_HALF
                                + r * 136 + seg * 8), src);
            }
            asm volatile("cp.async.commit_group;" ::: "memory");
            asm volatile("cp.async.wait_group 1;" ::: "memory");
        } else {
            asm volatile("cp.async.wait_group 0;" ::: "memory");
        }
        __syncthreads();
#pragma unroll
        for (int ks = 0; ks < 2; ks++) {
            int k0 = kt * 32 + ks * 16;
            uint32_t Ah[2][4], Al[2][4], Bh[2][4], Bl[2][4];
#pragma unroll
            for (int mt = 0; mt < 2; mt++) {
                uint32_t addr = sAu + 2 * ((wm + mt * 16 + a_lr) * 200 + k0 + a_kh);
                ldsm4(Ah[mt], addr);
                ldsm4(Al[mt], addr + 2 * AS_HALF);
            }
#pragma unroll
            for (int j = 0; j < 2; j++) {
                uint32_t addr = sBu + 2 * (buf * BS_BUF
                    + (ks * 16 + a_lr) * 136 + wn + j * 16 + a_kh);
                ldsm4t(Bh[j], addr);
                ldsm4t(Bl[j], addr + 2 * BS_HALF);
            }
#pragma unroll
            for (int mt = 0; mt < 2; mt++)
#pragma unroll
                for (int j = 0; j < 2; j++)
#pragma unroll
                    for (int hn = 0; hn < 2; hn++) {
                        float* c = acc[mt][j * 2 + hn];
                        mma16816(c, Ah[mt], &Bh[j][hn * 2]);
                        mma16816(c, Ah[mt], &Bl[j][hn * 2]);
                        mma16816(c, Al[mt], &Bh[j][hn * 2]);
                    }
        }
        __syncthreads();
    }

    int g = lane >> 2, tg = lane & 3;
#pragma unroll
    for (int mt = 0; mt < 2; mt++) {
        int row = m0 + wm + mt * 16 + g;
#pragma unroll
        for (int nt = 0; nt < 4; nt++) {
            int col = n0 + wn + nt * 8 + tg * 2;
            float* c = acc[mt][nt];
            *(float2*)&C[(size_t)row * N + col]       = make_float2(c[0], c[1]);
            *(float2*)&C[(size_t)(row + 8) * N + col] = make_float2(c[2], c[3]);
        }
    }
}

// ------- K3: depthwise 3x3, 4 rows/thread; q,k -> f32(+mask+sumsq), v -> bf16 -------
__global__ void __launch_bounds__(128) dw_kernel(
    const float* __restrict__ in, const float* __restrict__ dww,
    const float* __restrict__ mask, float* __restrict__ out,
    float* __restrict__ ssp,
    __nv_bfloat16* __restrict__ vhi, __nv_bfloat16* __restrict__ vlo)
{
    int xx = threadIdx.x;
    int y0 = blockIdx.x * 4;
    int oc = blockIdx.y, b = blockIdx.z;
    size_t base = ((size_t)b * C3 + oc) * HW;
    float w[9];
#pragma unroll
    for (int i = 0; i < 9; i++) w[i] = __ldg(&dww[oc * 9 + i]);
    float cl[6], cm[6], cr[6];
#pragma unroll
    for (int i = 0; i < 6; i++) {
        int yy = y0 - 1 + i;
        bool vy = (yy >= 0) && (yy < HH);
        const float* rp = in + base + (size_t)yy * WW;
        cm[i] = vy ? rp[xx] : 0.f;
        cl[i] = (vy && xx > 0)      ? rp[xx - 1] : 0.f;
        cr[i] = (vy && xx < WW - 1) ? rp[xx + 1] : 0.f;
    }
    float acc[4];
#pragma unroll
    for (int r = 0; r < 4; r++) {
        float a = 0.f;
#pragma unroll
        for (int j = 0; j < 3; j++)
            a += cl[r+j]*w[j*3] + cm[r+j]*w[j*3+1] + cr[r+j]*w[j*3+2];
        acc[r] = a;
    }
    if (oc < 2 * CC) {          // q or k: apply mask, f32 out, sumsq partials
        float ss = 0.f;
#pragma unroll
        for (int r = 0; r < 4; r++) {
            float mv = mask[(size_t)b * HW + (y0 + r) * WW + xx];
            acc[r] *= mv;
            ss += acc[r] * acc[r];
        }
#pragma unroll
        for (int o = 16; o; o >>= 1) ss += __shfl_down_sync(0xffffffffu, ss, o);
        __shared__ float red[4];
        if ((xx & 31) == 0) red[xx >> 5] = ss;
        __syncthreads();
        if (xx == 0)
            ssp[(size_t)(b * 2 * CC + oc) * 32 + blockIdx.x] =
                red[0] + red[1] + red[2] + red[3];
        size_t ob = ((size_t)b * 2 * CC + oc) * HW;
#pragma unroll
        for (int r = 0; r < 4; r++)
            out[ob + (size_t)(y0 + r) * WW + xx] = acc[r];
    } else {                    // v: write split bf16 directly
        size_t vb = ((size_t)b * GK + (oc - 2 * CC)) * HW;
#pragma unroll
        for (int r = 0; r < 4; r++) {
            __nv_bfloat16 h = __float2bfloat16(acc[r]);
            vhi[vb + (size_t)(y0 + r) * WW + xx] = h;
            vlo[vb + (size_t)(y0 + r) * WW + xx] =
                __float2bfloat16(acc[r] - __bfloat162float(h));
        }
    }
}

// ---------------- K3b: sumsq reduce ----------------
__global__ void __launch_bounds__(32) ssreduce_kernel(
    const float* __restrict__ part, float* __restrict__ sumsq)
{
    int id = blockIdx.x, t = threadIdx.x;
    float v = part[(size_t)id * 32 + t];
#pragma unroll
    for (int o = 16; o; o >>= 1) v += __shfl_down_sync(0xffffffffu, v, o);
    if (t == 0) sumsq[id] = v;
}

// ---------------- K4: QK^T partials (f32x2) ----------------
__global__ void __launch_bounds__(64) qk_kernel(
    const float* __restrict__ qk, float* __restrict__ Spart)
{
    int chunk = blockIdx.x, h = blockIdx.y, b = blockIdx.z;
    const float* qbase = qk + ((size_t)b * 2 * CC + h * CH) * HW;
    const float* kbase = qk + ((size_t)b * 2 * CC + CC + h * CH) * HW;
    int p0 = chunk * 512;
    __shared__ float qs[CH][34];
    __shared__ float ks[CH][34];
    int t = threadIdx.x, ti = t >> 3, tj = t & 7;
    unsigned long long acc[6][6];
#pragma unroll
    for (int i = 0; i < 6; i++)
#pragma unroll
        for (int j = 0; j < 6; j++) acc[i][j] = 0ULL;
    for (int sub = 0; sub < 16; sub++) {
        int pp = p0 + sub * 32;
        __syncthreads();
#pragma unroll
        for (int j = 0; j < 6; j++) {
            int id = t + j * 64;
            int row = id >> 3, c4 = (id & 7) * 4;
            float4 v = *(const float4*)(qbase + (size_t)row * HW + pp + c4);
            qs[row][c4] = v.x; qs[row][c4+1] = v.y;
            qs[row][c4+2] = v.z; qs[row][c4+3] = v.w;
            float4 w = *(const float4*)(kbase + (size_t)row * HW + pp + c4);
            ks[row][c4] = w.x; ks[row][c4+1] = w.y;
            ks[row][c4+2] = w.z; ks[row][c4+3] = w.w;
        }
        __syncthreads();
#pragma unroll
        for (int kk = 0; kk < 16; kk++) {
            unsigned long long q2[6], k2[6];
#pragma unroll
            for (int i = 0; i < 6; i++)
                q2[i] = *(const unsigned long long*)&qs[ti * 6 + i][kk * 2];
#pragma unroll
            for (int j = 0; j < 6; j++)
                k2[j] = *(const unsigned long long*)&ks[tj * 6 + j][kk * 2];
#pragma unroll
            for (int i = 0; i < 6; i++)
#pragma unroll
                for (int j = 0; j < 6; j++)
                    acc[i][j] = fma2(q2[i], k2[j], acc[i][j]);
        }
    }
    float* Sp = Spart + (size_t)chunk * (BB * NHEADS * CH * CH)
                      + (size_t)(b * NHEADS + h) * (CH * CH);
#pragma unroll
    for (int i = 0; i < 6; i++)
#pragma unroll
        for (int j = 0; j < 6; j++) {
            float2 f = unpack2(acc[i][j]);
            Sp[(ti * 6 + i) * CH + tj * 6 + j] = f.x + f.y;
        }
}

// ------ K5: reduce S + cosine scale + softmax + fold proj -> M (bf16 hi/lo) --------
__global__ void __launch_bounds__(256) attn_kernel(
    const float* __restrict__ Spart, const float* __restrict__ sumsq,
    const float* __restrict__ temp, const float* __restrict__ projw,
    __nv_bfloat16* __restrict__ Mhi, __nv_bfloat16* __restrict__ Mlo)
{
    int h = blockIdx.x, b = blockIdx.y;
    __shared__ float att[CH][CH];
    __shared__ float rnq[CH], rnk[CH];
    int t = threadIdx.x;
    if (t < CH) {
        float nq = sqrtf(sumsq[b * 2 * CC + h * CH + t]);
        float nk = sqrtf(sumsq[b * 2 * CC + CC + h * CH + t]);
        rnq[t] = 1.f / fmaxf(nq, 1e-12f);
        rnk[t] = 1.f / fmaxf(nk, 1e-12f);
    }
    __syncthreads();
    float T = temp[h];
    size_t sp0 = (size_t)(b * NHEADS + h) * (CH * CH);
    for (int i = t; i < CH * CH; i += 256) {
        float s = 0.f;
#pragma unroll
        for (int c = 0; c < 32; c++)
            s += Spart[(size_t)c * (BB * NHEADS * CH * CH) + sp0 + i];
        int cR = i / CH, d = i % CH;
        att[cR][d] = s * rnq[cR] * rnk[d] * T;
    }
    __syncthreads();
    if (t < CH) {
        float mx = -1e30f;
#pragma unroll
        for (int d = 0; d < CH; d++) mx = fmaxf(mx, att[t][d]);
        float sum = 0.f;
#pragma unroll
        for (int d = 0; d < CH; d++) {
            float e = expf(att[t][d] - mx);
            att[t][d] = e;
            sum += e;
        }
        float inv = 1.f / sum;
#pragma unroll
        for (int d = 0; d < CH; d++) att[t][d] *= inv;
    }
    __syncthreads();
    for (int i = t; i < CC * CH; i += 256) {
        int o = i / CH, d = i % CH;
        float s = 0.f;
#pragma unroll
        for (int c = 0; c < CH; c++)
            s += projw[o * CC + h * CH + c] * att[c][d];
        size_t idx = ((size_t)b * CC + o) * CC + h * CH + d;
        __nv_bfloat16 hi = __float2bfloat16(s);
        Mhi[idx] = hi;
        Mlo[idx] = __float2bfloat16(s - __bfloat162float(hi));
    }
}

// ---------------- launch ----------------
extern "C" void kernel_launch(void* const* d_in, const int* in_sizes, int n_in,
                              void* d_out, int out_size)
{
    const float* x     = (const float*)d_in[0];
    const float* inp   = (const float*)d_in[1];
    const float* qkvw  = (const float*)d_in[2];
    const float* dww   = (const float*)d_in[3];
    const float* projw = (const float*)d_in[4];
    const float* cmw   = (const float*)d_in[5];
    const float* temp  = (const float*)d_in[6];
    const float* thr   = (const float*)d_in[7];
    float* out = (float*)d_out;

    float *p_mask, *p_qkv, *p_qkvd, *p_ssp, *p_sumsq, *p_spart;
    __nv_bfloat16 *p_whi, *p_wlo, *p_xhi, *p_xlo, *p_vhi, *p_vlo, *p_mhi, *p_mlo;
    cudaGetSymbolAddress((void**)&p_mask,  g_mask);
    cudaGetSymbolAddress((void**)&p_qkv,   g_qkv);
    cudaGetSymbolAddress((void**)&p_qkvd,  g_qkvd);
    cudaGetSymbolAddress((void**)&p_ssp,   g_ssp);
    cudaGetSymbolAddress((void**)&p_sumsq, g_sumsq);
    cudaGetSymbolAddress((void**)&p_spart, g_Spart);
    cudaGetSymbolAddress((void**)&p_whi,   g_Whi);
    cudaGetSymbolAddress((void**)&p_wlo,   g_Wlo);
    cudaGetSymbolAddress((void**)&p_xhi,   g_xhi);
    cudaGetSymbolAddress((void**)&p_xlo,   g_xlo);
    cudaGetSymbolAddress((void**)&p_vhi,   g_vhi);
    cudaGetSymbolAddress((void**)&p_vlo,   g_vlo);
    cudaGetSymbolAddress((void**)&p_mhi,   g_Mhi);
    cudaGetSymbolAddress((void**)&p_mlo,   g_Mlo);

    cudaFuncSetAttribute(gemm_hmma,
        cudaFuncAttributeMaxDynamicSharedMemorySize, GEMM_SMEM);

    // K1: mask
    mask_kernel<<<dim3(HW / 256, BB), 256>>>(x, inp, cmw, thr, p_mask);
    // converts for K2
    convw_kernel<<<C3, 192>>>(qkvw, p_whi, p_wlo);
    convb_kernel<<<dim3(GK * HW / (256 * 8), BB), 256>>>(
        x, (size_t)CC * HW, p_xhi, p_xlo);
    // K2: qkv = W @ x  (tensor cores, bf16 split x3)
    gemm_hmma<<<dim3(HW / 128, C3 / 64, BB), 256, GEMM_SMEM>>>(
        p_whi, p_wlo, (size_t)0, p_xhi, p_xlo, (size_t)GK * HW,
        p_qkv, (size_t)C3 * HW);
    // K3: depthwise 3x3; q,k -> f32 + mask + sumsq; v -> bf16 hi/lo
    dw_kernel<<<dim3(HH / 4, C3, BB), 128>>>(p_qkv, dww, p_mask, p_qkvd, p_ssp,
                                             p_vhi, p_vlo);
    ssreduce_kernel<<<BB * 2 * CC, 32>>>(p_ssp, p_sumsq);
    // K4: S partials
    qk_kernel<<<dim3(32, NHEADS, BB), 64>>>(p_qkvd, p_spart);
    // K5: softmax + fold proj -> bf16 hi/lo M
    attn_kernel<<<dim3(NHEADS, BB), 256>>>(p_spart, p_sumsq, temp, projw,
                                           p_mhi, p_mlo);
    // K6: out = M @ v  (tensor cores)
    gemm_hmma<<<dim3(HW / 128, CC / 64, BB), 256, GEMM_SMEM>>>(
        p_mhi, p_mlo, (size_t)CC * CC, p_vhi, p_vlo, (size_t)GK * HW,
        out, (size_t)CC * HW);
}

// round 15
// speedup vs baseline: 1.0053x; 1.0051x over previous
#include <cuda_runtime.h>
#include <cuda_bf16.h>
#include <cstdint>
#include <cstddef>

#define HH 128
#define WW 128
#define HW 16384
#define CC 192
#define C3 576
#define BB 8
#define NHEADS 4
#define CH 48
#define GK 192

// gemm tiling
#define AS_HALF (64 * 200)          // A smem elems per half (64 rows, 192+8 pad)
#define BS_HALF (32 * 136)          // B smem elems per half per buf (32 rows, 128+8 pad)
#define BS_BUF  (2 * BS_HALF)
#define GEMM_SMEM ((2 * AS_HALF + 2 * BS_BUF) * 2)   // 86016 bytes

// ---------------- scratch (static device globals) ----------------
__device__ float g_mask[BB * HW];
__device__ float g_qkv [(size_t)BB * C3 * HW];
__device__ float g_qkvd[(size_t)BB * 2 * CC * HW];   // only q,k kept in f32
__device__ float g_ssp [BB * 2 * CC * 32];
__device__ float g_sumsq[BB * 2 * CC];
__device__ float g_Spart[(size_t)32 * BB * NHEADS * CH * CH];
__device__ __nv_bfloat16 g_Whi[C3 * GK];
__device__ __nv_bfloat16 g_Wlo[C3 * GK];
__device__ __nv_bfloat16 g_xhi[(size_t)BB * GK * HW];
__device__ __nv_bfloat16 g_xlo[(size_t)BB * GK * HW];
__device__ __nv_bfloat16 g_vhi[(size_t)BB * GK * HW];
__device__ __nv_bfloat16 g_vlo[(size_t)BB * GK * HW];
__device__ __nv_bfloat16 g_Mhi[BB * CC * CC];
__device__ __nv_bfloat16 g_Mlo[BB * CC * CC];

// ---------------- helpers ----------------
__device__ __forceinline__ unsigned long long fma2(unsigned long long a,
                                                   unsigned long long b,
                                                   unsigned long long c) {
    unsigned long long d;
    asm("fma.rn.f32x2 %0, %1, %2, %3;" : "=l"(d) : "l"(a), "l"(b), "l"(c));
    return d;
}
__device__ __forceinline__ float2 unpack2(unsigned long long v) {
    float2 r;
    asm("mov.b64 {%0, %1}, %2;" : "=f"(r.x), "=f"(r.y) : "l"(v));
    return r;
}
__device__ __forceinline__ uint32_t smem_u32(const void* p) {
    uint32_t a;
    asm("{ .reg .u64 t; cvta.to.shared.u64 t, %1; cvt.u32.u64 %0, t; }"
        : "=r"(a) : "l"(p));
    return a;
}
__device__ __forceinline__ void cp16(uint32_t dst, const void* src) {
    asm volatile("cp.async.cg.shared.global [%0], [%1], 16;"
                 :: "r"(dst), "l"(src));
}
__device__ __forceinline__ void ldsm4(uint32_t* r, uint32_t a) {
    asm volatile("ldmatrix.sync.aligned.m8n8.x4.shared.b16 {%0,%1,%2,%3}, [%4];"
        : "=r"(r[0]), "=r"(r[1]), "=r"(r[2]), "=r"(r[3]) : "r"(a));
}
__device__ __forceinline__ void ldsm4t(uint32_t* r, uint32_t a) {
    asm volatile("ldmatrix.sync.aligned.m8n8.x4.trans.shared.b16 {%0,%1,%2,%3}, [%4];"
        : "=r"(r[0]), "=r"(r[1]), "=r"(r[2]), "=r"(r[3]) : "r"(a));
}
__device__ __forceinline__ void mma16816(float* c, const uint32_t* a,
                                         const uint32_t* b) {
    asm volatile(
        "mma.sync.aligned.m16n8k16.row.col.f32.bf16.bf16.f32 "
        "{%0,%1,%2,%3}, {%4,%5,%6,%7}, {%8,%9}, {%0,%1,%2,%3};"
        : "+f"(c[0]), "+f"(c[1]), "+f"(c[2]), "+f"(c[3])
        : "r"(a[0]), "r"(a[1]), "r"(a[2]), "r"(a[3]), "r"(b[0]), "r"(b[1]));
}

// ---------------- K1: mask ----------------
__global__ void __launch_bounds__(256) mask_kernel(
    const float* __restrict__ x, const float* __restrict__ inp,
    const float* __restrict__ cmw, const float* __restrict__ thr_p,
    float* __restrict__ mask)
{
    __shared__ float cw[CC];
    int t = threadIdx.x;
    if (t < CC) cw[t] = cmw[t];
    __syncthreads();
    float thr = *thr_p;
    int p = blockIdx.x * 256 + t;
    int b = blockIdx.y;
    size_t off = (size_t)b * CC * HW + p;
    float acc = 0.f;
#pragma unroll 4
    for (int c = 0; c < CC; c++) {
        float d = inp[off + (size_t)c * HW] - x[off + (size_t)c * HW];
        acc += (d > thr) ? cw[c] : 0.f;
    }
    mask[(size_t)b * HW + p] = acc;
}

// ---------------- convert W [576][192] f32 -> bf16 hi/lo ----------------
__global__ void __launch_bounds__(192) convw_kernel(
    const float* __restrict__ W, __nv_bfloat16* __restrict__ whi,
    __nv_bfloat16* __restrict__ wlo)
{
    int i = blockIdx.x * 192 + threadIdx.x;
    float v = W[i];
    __nv_bfloat16 h = __float2bfloat16(v);
    whi[i] = h;
    wlo[i] = __float2bfloat16(v - __bfloat162float(h));
}

// ------- convert B [192][16384] f32 -> bf16 hi/lo, same layout (8 elems/thread) -----
__global__ void __launch_bounds__(256) convb_kernel(
    const float* __restrict__ in, size_t sIn,
    __nv_bfloat16* __restrict__ ohi, __nv_bfloat16* __restrict__ olo)
{
    size_t e0 = ((size_t)blockIdx.x * 256 + threadIdx.x) * 8;
    int b = blockIdx.y;
    const float4* src = (const float4*)(in + (size_t)b * sIn + e0);
    float4 v0 = src[0], v1 = src[1];
    float vv[8] = {v0.x, v0.y, v0.z, v0.w, v1.x, v1.y, v1.z, v1.w};
    __nv_bfloat16 hb[8], lb[8];
#pragma unroll
    for (int i = 0; i < 8; i++) {
        hb[i] = __float2bfloat16(vv[i]);
        lb[i] = __float2bfloat16(vv[i] - __bfloat162float(hb[i]));
    }
    size_t o = (size_t)b * GK * HW + e0;
    *(uint4*)(ohi + o) = *(const uint4*)hb;
    *(uint4*)(olo + o) = *(const uint4*)lb;
}

// ------------- HMMA bf16-split GEMM: C[M,16384] = A[M,192] @ B[192,16384] -----------
// CTA: M=64, N=128, 8 warps (warp tile 32x32). A resident; B double-buffered k32.
// 3 passes hi*hi + hi*lo + lo*hi fused in the k-loop.
__global__ void __launch_bounds__(256) gemm_hmma(
    const __nv_bfloat16* __restrict__ Ahi, const __nv_bfloat16* __restrict__ Alo,
    size_t sA,
    const __nv_bfloat16* __restrict__ Bhi, const __nv_bfloat16* __restrict__ Blo,
    size_t sB, float* __restrict__ C, size_t sC)
{
    extern __shared__ __nv_bfloat16 sm[];
    __nv_bfloat16* As = sm;                    // [2 half][64][200]
    __nv_bfloat16* Bs = sm + 2 * AS_HALF;      // [2 buf][2 half][32][136]
    const int N = HW;
    int b = blockIdx.z;
    Ahi += (size_t)b * sA; Alo += (size_t)b * sA;
    Bhi += (size_t)b * sB; Blo += (size_t)b * sB;
    C   += (size_t)b * sC;
    int n0 = blockIdx.x * 128, m0 = blockIdx.y * 64;
    int tid = threadIdx.x, lane = tid & 31, w = tid >> 5;
    int wm = (w & 1) * 32;          // 2 warps along M
    int wn = (w >> 1) * 32;         // 4 warps along N
    uint32_t sAu = smem_u32(As), sBu = smem_u32(Bs);

    // ---- prefetch B chunk 0 (group 0) ----
#pragma unroll
    for (int i = 0; i < 4; i++) {
        int idx = tid + i * 256;               // 0..1023
        int half = idx >> 9, r = (idx >> 4) & 31, seg = idx & 15;
        const __nv_bfloat16* src =
            (half ? Blo : Bhi) + (size_t)r * N + n0 + seg * 8;
        cp16(sBu + 2 * (half * BS_HALF + r * 136 + seg * 8), src);
    }
    asm volatile("cp.async.commit_group;" ::: "memory");
    // ---- stage A (group 1) ----
#pragma unroll
    for (int i = 0; i < 12; i++) {
        int idx = tid + i * 256;               // 0..3071
        int half = idx >= 1536;
        int r = (idx - half * 1536) / 24;
        int seg = idx % 24;
        const __nv_bfloat16* src =
            (half ? Alo : Ahi) + (size_t)(m0 + r) * GK + seg * 8;
        cp16(sAu + 2 * (half * AS_HALF + r * 200 + seg * 8), src);
    }
    asm volatile("cp.async.commit_group;" ::: "memory");

    float acc[2][4][4];
#pragma unroll
    for (int i = 0; i < 2; i++)
#pragma unroll
        for (int j = 0; j < 4; j++)
#pragma unroll
            for (int q = 0; q < 4; q++) acc[i][j][q] = 0.f;

    int a_lr = (lane & 15), a_kh = (lane >> 4) << 3;

    for (int kt = 0; kt < 6; kt++) {
        int buf = kt & 1;
        if (kt < 5) {
#pragma unroll
            for (int i = 0; i < 4; i++) {
                int idx = tid + i * 256;
                int half = idx >> 9, r = (idx >> 4) & 31, seg = idx & 15;
                const __nv_bfloat16* src = (half ? Blo : Bhi)
                    + (size_t)((kt + 1) * 32 + r) * N + n0 + seg * 8;
                cp16(sBu + 2 * ((buf ^ 1) * BS_BUF + half * BS_HALF
                                + r * 136 + seg * 8), src);
            }
            asm volatile("cp.async.commit_group;" ::: "memory");
            asm volatile("cp.async.wait_group 1;" ::: "memory");
        } else {
            asm volatile("cp.async.wait_group 0;" ::: "memory");
        }
        __syncthreads();
#pragma unroll
        for (int ks = 0; ks < 2; ks++) {
            int k0 = kt * 32 + ks * 16;
            uint32_t Ah[2][4], Al[2][4], Bh[2][4], Bl[2][4];
#pragma unroll
            for (int mt = 0; mt < 2; mt++) {
                uint32_t addr = sAu + 2 * ((wm + mt * 16 + a_lr) * 200 + k0 + a_kh);
                ldsm4(Ah[mt], addr);
                ldsm4(Al[mt], addr + 2 * AS_HALF);
            }
#pragma unroll
            for (int j = 0; j < 2; j++) {
                uint32_t addr = sBu + 2 * (buf * BS_BUF
                    + (ks * 16 + a_lr) * 136 + wn + j * 16 + a_kh);
                ldsm4t(Bh[j], addr);
                ldsm4t(Bl[j], addr + 2 * BS_HALF);
            }
#pragma unroll
            for (int mt = 0; mt < 2; mt++)
#pragma unroll
                for (int j = 0; j < 2; j++)
#pragma unroll
                    for (int hn = 0; hn < 2; hn++) {
                        float* c = acc[mt][j * 2 + hn];
                        mma16816(c, Ah[mt], &Bh[j][hn * 2]);
                        mma16816(c, Ah[mt], &Bl[j][hn * 2]);
                        mma16816(c, Al[mt], &Bh[j][hn * 2]);
                    }
        }
        __syncthreads();
    }

    int g = lane >> 2, tg = lane & 3;
#pragma unroll
    for (int mt = 0; mt < 2; mt++) {
        int row = m0 + wm + mt * 16 + g;
#pragma unroll
        for (int nt = 0; nt < 4; nt++) {
            int col = n0 + wn + nt * 8 + tg * 2;
            float* c = acc[mt][nt];
            *(float2*)&C[(size_t)row * N + col]       = make_float2(c[0], c[1]);
            *(float2*)&C[(size_t)(row + 8) * N + col] = make_float2(c[2], c[3]);
        }
    }
}

// ------- K3: depthwise 3x3, 4 rows/thread; q,k -> f32(+mask+sumsq), v -> bf16 -------
__global__ void __launch_bounds__(128) dw_kernel(
    const float* __restrict__ in, const float* __restrict__ dww,
    const float* __restrict__ mask, float* __restrict__ out,
    float* __restrict__ ssp,
    __nv_bfloat16* __restrict__ vhi, __nv_bfloat16* __restrict__ vlo)
{
    int xx = threadIdx.x;
    int y0 = blockIdx.x * 4;
    int oc = blockIdx.y, b = blockIdx.z;
    size_t base = ((size_t)b * C3 + oc) * HW;
    float w[9];
#pragma unroll
    for (int i = 0; i < 9; i++) w[i] = __ldg(&dww[oc * 9 + i]);
    float cl[6], cm[6], cr[6];
#pragma unroll
    for (int i = 0; i < 6; i++) {
        int yy = y0 - 1 + i;
        bool vy = (yy >= 0) && (yy < HH);
        const float* rp = in + base + (size_t)yy * WW;
        cm[i] = vy ? rp[xx] : 0.f;
        cl[i] = (vy && xx > 0)      ? rp[xx - 1] : 0.f;
        cr[i] = (vy && xx < WW - 1) ? rp[xx + 1] : 0.f;
    }
    float acc[4];
#pragma unroll
    for (int r = 0; r < 4; r++) {
        float a = 0.f;
#pragma unroll
        for (int j = 0; j < 3; j++)
            a += cl[r+j]*w[j*3] + cm[r+j]*w[j*3+1] + cr[r+j]*w[j*3+2];
        acc[r] = a;
    }
    if (oc < 2 * CC) {          // q or k: apply mask, f32 out, sumsq partials
        float ss = 0.f;
#pragma unroll
        for (int r = 0; r < 4; r++) {
            float mv = mask[(size_t)b * HW + (y0 + r) * WW + xx];
            acc[r] *= mv;
            ss += acc[r] * acc[r];
        }
#pragma unroll
        for (int o = 16; o; o >>= 1) ss += __shfl_down_sync(0xffffffffu, ss, o);
        __shared__ float red[4];
        if ((xx & 31) == 0) red[xx >> 5] = ss;
        __syncthreads();
        if (xx == 0)
            ssp[(size_t)(b * 2 * CC + oc) * 32 + blockIdx.x] =
                red[0] + red[1] + red[2] + red[3];
        size_t ob = ((size_t)b * 2 * CC + oc) * HW;
#pragma unroll
        for (int r = 0; r < 4; r++)
            out[ob + (size_t)(y0 + r) * WW + xx] = acc[r];
    } else {                    // v: write split bf16 directly
        size_t vb = ((size_t)b * GK + (oc - 2 * CC)) * HW;
#pragma unroll
        for (int r = 0; r < 4; r++) {
            __nv_bfloat16 h = __float2bfloat16(acc[r]);
            vhi[vb + (size_t)(y0 + r) * WW + xx] = h;
            vlo[vb + (size_t)(y0 + r) * WW + xx] =
                __float2bfloat16(acc[r] - __bfloat162float(h));
        }
    }
}

// ---------------- K3b: sumsq reduce ----------------
__global__ void __launch_bounds__(32) ssreduce_kernel(
    const float* __restrict__ part, float* __restrict__ sumsq)
{
    int id = blockIdx.x, t = threadIdx.x;
    float v = part[(size_t)id * 32 + t];
#pragma unroll
    for (int o = 16; o; o >>= 1) v += __shfl_down_sync(0xffffffffu, v, o);
    if (t == 0) sumsq[id] = v;
}

// ---------------- K4: QK^T partials (f32x2) ----------------
__global__ void __launch_bounds__(64) qk_kernel(
    const float* __restrict__ qk, float* __restrict__ Spart)
{
    int chunk = blockIdx.x, h = blockIdx.y, b = blockIdx.z;
    const float* qbase = qk + ((size_t)b * 2 * CC + h * CH) * HW;
    const float* kbase = qk + ((size_t)b * 2 * CC + CC + h * CH) * HW;
    int p0 = chunk * 512;
    __shared__ float qs[CH][34];
    __shared__ float ks[CH][34];
    int t = threadIdx.x, ti = t >> 3, tj = t & 7;
    unsigned long long acc[6][6];
#pragma unroll
    for (int i = 0; i < 6; i++)
#pragma unroll
        for (int j = 0; j < 6; j++) acc[i][j] = 0ULL;
    for (int sub = 0; sub < 16; sub++) {
        int pp = p0 + sub * 32;
        __syncthreads();
#pragma unroll
        for (int j = 0; j < 6; j++) {
            int id = t + j * 64;
            int row = id >> 3, c4 = (id & 7) * 4;
            float4 v = *(const float4*)(qbase + (size_t)row * HW + pp + c4);
            qs[row][c4] = v.x; qs[row][c4+1] = v.y;
            qs[row][c4+2] = v.z; qs[row][c4+3] = v.w;
            float4 w = *(const float4*)(kbase + (size_t)row * HW + pp + c4);
            ks[row][c4] = w.x; ks[row][c4+1] = w.y;
            ks[row][c4+2] = w.z; ks[row][c4+3] = w.w;
        }
        __syncthreads();
#pragma unroll
        for (int kk = 0; kk < 16; kk++) {
            unsigned long long q2[6], k2[6];
#pragma unroll
            for (int i = 0; i < 6; i++)
                q2[i] = *(const unsigned long long*)&qs[ti * 6 + i][kk * 2];
#pragma unroll
            for (int j = 0; j < 6; j++)
                k2[j] = *(const unsigned long long*)&ks[tj * 6 + j][kk * 2];
#pragma unroll
            for (int i = 0; i < 6; i++)
#pragma unroll
                for (int j = 0; j < 6; j++)
                    acc[i][j] = fma2(q2[i], k2[j], acc[i][j]);
        }
    }
    float* Sp = Spart + (size_t)chunk * (BB * NHEADS * CH * CH)
                      + (size_t)(b * NHEADS + h) * (CH * CH);
#pragma unroll
    for (int i = 0; i < 6; i++)
#pragma unroll
        for (int j = 0; j < 6; j++) {
            float2 f = unpack2(acc[i][j]);
            Sp[(ti * 6 + i) * CH + tj * 6 + j] = f.x + f.y;
        }
}

// ------ K5: reduce S + cosine scale + softmax + fold proj -> M (bf16 hi/lo) --------
__global__ void __launch_bounds__(256) attn_kernel(
    const float* __restrict__ Spart, const float* __restrict__ sumsq,
    const float* __restrict__ temp, const float* __restrict__ projw,
    __nv_bfloat16* __restrict__ Mhi, __nv_bfloat16* __restrict__ Mlo)
{
    int h = blockIdx.x, b = blockIdx.y;
    __shared__ float att[CH][CH];
    __shared__ float rnq[CH], rnk[CH];
    int t = threadIdx.x;
    if (t < CH) {
        float nq = sqrtf(sumsq[b * 2 * CC + h * CH + t]);
        float nk = sqrtf(sumsq[b * 2 * CC + CC + h * CH + t]);
        rnq[t] = 1.f / fmaxf(nq, 1e-12f);
        rnk[t] = 1.f / fmaxf(nk, 1e-12f);
    }
    __syncthreads();
    float T = temp[h];
    size_t sp0 = (size_t)(b * NHEADS + h) * (CH * CH);
    for (int i = t; i < CH * CH; i += 256) {
        float s = 0.f;
#pragma unroll
        for (int c = 0; c < 32; c++)
            s += Spart[(size_t)c * (BB * NHEADS * CH * CH) + sp0 + i];
        int cR = i / CH, d = i % CH;
        att[cR][d] = s * rnq[cR] * rnk[d] * T;
    }
    __syncthreads();
    if (t < CH) {
        float mx = -1e30f;
#pragma unroll
        for (int d = 0; d < CH; d++) mx = fmaxf(mx, att[t][d]);
        float sum = 0.f;
#pragma unroll
        for (int d = 0; d < CH; d++) {
            float e = expf(att[t][d] - mx);
            att[t][d] = e;
            sum += e;
        }
        float inv = 1.f / sum;
#pragma unroll
        for (int d = 0; d < CH; d++) att[t][d] *= inv;
    }
    __syncthreads();
    for (int i = t; i < CC * CH; i += 256) {
        int o = i / CH, d = i % CH;
        float s = 0.f;
#pragma unroll
        for (int c = 0; c < CH; c++)
            s += projw[o * CC + h * CH + c] * att[c][d];
        size_t idx = ((size_t)b * CC + o) * CC + h * CH + d;
        __nv_bfloat16 hi = __float2bfloat16(s);
        Mhi[idx] = hi;
        Mlo[idx] = __float2bfloat16(s - __bfloat162float(hi));
    }
}

// ---------------- launch ----------------
extern "C" void kernel_launch(void* const* d_in, const int* in_sizes, int n_in,
                              void* d_out, int out_size)
{
    const float* x     = (const float*)d_in[0];
    const float* inp   = (const float*)d_in[1];
    const float* qkvw  = (const float*)d_in[2];
    const float* dww   = (const float*)d_in[3];
    const float* projw = (const float*)d_in[4];
    const float* cmw   = (const float*)d_in[5];
    const float* temp  = (const float*)d_in[6];
    const float* thr   = (const float*)d_in[7];
    float* out = (float*)d_out;

    float *p_mask, *p_qkv, *p_qkvd, *p_ssp, *p_sumsq, *p_spart;
    __nv_bfloat16 *p_whi, *p_wlo, *p_xhi, *p_xlo, *p_vhi, *p_vlo, *p_mhi, *p_mlo;
    cudaGetSymbolAddress((void**)&p_mask,  g_mask);
    cudaGetSymbolAddress((void**)&p_qkv,   g_qkv);
    cudaGetSymbolAddress((void**)&p_qkvd,  g_qkvd);
    cudaGetSymbolAddress((void**)&p_ssp,   g_ssp);
    cudaGetSymbolAddress((void**)&p_sumsq, g_sumsq);
    cudaGetSymbolAddress((void**)&p_spart, g_Spart);
    cudaGetSymbolAddress((void**)&p_whi,   g_Whi);
    cudaGetSymbolAddress((void**)&p_wlo,   g_Wlo);
    cudaGetSymbolAddress((void**)&p_xhi,   g_xhi);
    cudaGetSymbolAddress((void**)&p_xlo,   g_xlo);
    cudaGetSymbolAddress((void**)&p_vhi,   g_vhi);
    cudaGetSymbolAddress((void**)&p_vlo,   g_vlo);
    cudaGetSymbolAddress((void**)&p_mhi,   g_Mhi);
    cudaGetSymbolAddress((void**)&p_mlo,   g_Mlo);

    cudaFuncSetAttribute(gemm_hmma,
        cudaFuncAttributeMaxDynamicSharedMemorySize, GEMM_SMEM);

    // K1: mask
    mask_kernel<<<dim3(HW / 256, BB), 256>>>(x, inp, cmw, thr, p_mask);
    // converts for K2
    convw_kernel<<<C3, 192>>>(qkvw, p_whi, p_wlo);
    convb_kernel<<<dim3(GK * HW / (256 * 8), BB), 256>>>(
        x, (size_t)CC * HW, p_xhi, p_xlo);
    // K2: qkv = W @ x  (tensor cores, bf16 split x3)
    gemm_hmma<<<dim3(HW / 128, C3 / 64, BB), 256, GEMM_SMEM>>>(
        p_whi, p_wlo, (size_t)0, p_xhi, p_xlo, (size_t)GK * HW,
        p_qkv, (size_t)C3 * HW);
    // K3: depthwise 3x3; q,k -> f32 + mask + sumsq; v -> bf16 hi/lo
    dw_kernel<<<dim3(HH / 4, C3, BB), 128>>>(p_qkv, dww, p_mask, p_qkvd, p_ssp,
                                             p_vhi, p_vlo);
    ssreduce_kernel<<<BB * 2 * CC, 32>>>(p_ssp, p_sumsq);
    // K4: S partials
    qk_kernel<<<dim3(32, NHEADS, BB), 64>>>(p_qkvd, p_spart);
    // K5: softmax + fold proj -> bf16 hi/lo M
    attn_kernel<<<dim3(NHEADS, BB), 256>>>(p_spart, p_sumsq, temp, projw,
                                           p_mhi, p_mlo);
    // K6: out = M @ v  (tensor cores)
    gemm_hmma<<<dim3(HW / 128, CC / 64, BB), 256, GEMM_SMEM>>>(
        p_mhi, p_mlo, (size_t)CC * CC, p_vhi, p_vlo, (size_t)GK * HW,
        out, (size_t)CC * HW);
}

// round 16
// speedup vs baseline: 1.0534x; 1.0479x over previous
#include <cuda_runtime.h>
#include <cuda_bf16.h>
#include <cstdint>
#include <cstddef>

#define HH 128
#define WW 128
#define HW 16384
#define CC 192
#define C3 576
#define BB 8
#define NHEADS 4
#define CH 48
#define GK 192

// gemm tiling
#define AS_HALF (64 * 200)          // A smem elems per half (64 rows, 192+8 pad)
#define BS_HALF (32 * 136)          // B smem elems per half per buf (32 rows, 128+8 pad)
#define BS_BUF  (2 * BS_HALF)
#define GEMM_SMEM ((2 * AS_HALF + 2 * BS_BUF) * 2)   // 86016 bytes

// ---------------- scratch (static device globals) ----------------
__device__ float g_mask[BB * HW];
__device__ float g_qkv [(size_t)BB * C3 * HW];
__device__ float g_qkvd[(size_t)BB * 2 * CC * HW];   // only q,k kept in f32
__device__ float g_ssp [BB * 2 * CC * 32];
__device__ float g_sumsq[BB * 2 * CC];
__device__ float g_Spart[(size_t)32 * BB * NHEADS * CH * CH];
__device__ __nv_bfloat16 g_Whi[C3 * GK];
__device__ __nv_bfloat16 g_Wlo[C3 * GK];
__device__ __nv_bfloat16 g_xhi[(size_t)BB * GK * HW];
__device__ __nv_bfloat16 g_xlo[(size_t)BB * GK * HW];
__device__ __nv_bfloat16 g_vhi[(size_t)BB * GK * HW];
__device__ __nv_bfloat16 g_vlo[(size_t)BB * GK * HW];
__device__ __nv_bfloat16 g_Mhi[BB * CC * CC];
__device__ __nv_bfloat16 g_Mlo[BB * CC * CC];

// ---------------- helpers ----------------
__device__ __forceinline__ unsigned long long fma2(unsigned long long a,
                                                   unsigned long long b,
                                                   unsigned long long c) {
    unsigned long long d;
    asm("fma.rn.f32x2 %0, %1, %2, %3;" : "=l"(d) : "l"(a), "l"(b), "l"(c));
    return d;
}
__device__ __forceinline__ float2 unpack2(unsigned long long v) {
    float2 r;
    asm("mov.b64 {%0, %1}, %2;" : "=f"(r.x), "=f"(r.y) : "l"(v));
    return r;
}
__device__ __forceinline__ uint32_t smem_u32(const void* p) {
    uint32_t a;
    asm("{ .reg .u64 t; cvta.to.shared.u64 t, %1; cvt.u32.u64 %0, t; }"
        : "=r"(a) : "l"(p));
    return a;
}
__device__ __forceinline__ void cp16(uint32_t dst, const void* src) {
    asm volatile("cp.async.cg.shared.global [%0], [%1], 16;"
                 :: "r"(dst), "l"(src));
}
__device__ __forceinline__ void ldsm4(uint32_t* r, uint32_t a) {
    asm volatile("ldmatrix.sync.aligned.m8n8.x4.shared.b16 {%0,%1,%2,%3}, [%4];"
        : "=r"(r[0]), "=r"(r[1]), "=r"(r[2]), "=r"(r[3]) : "r"(a));
}
__device__ __forceinline__ void ldsm4t(uint32_t* r, uint32_t a) {
    asm volatile("ldmatrix.sync.aligned.m8n8.x4.trans.shared.b16 {%0,%1,%2,%3}, [%4];"
        : "=r"(r[0]), "=r"(r[1]), "=r"(r[2]), "=r"(r[3]) : "r"(a));
}
__device__ __forceinline__ void mma16816(float* c, const uint32_t* a,
                                         const uint32_t* b) {
    asm volatile(
        "mma.sync.aligned.m16n8k16.row.col.f32.bf16.bf16.f32 "
        "{%0,%1,%2,%3}, {%4,%5,%6,%7}, {%8,%9}, {%0,%1,%2,%3};"
        : "+f"(c[0]), "+f"(c[1]), "+f"(c[2]), "+f"(c[3])
        : "r"(a[0]), "r"(a[1]), "r"(a[2]), "r"(a[3]), "r"(b[0]), "r"(b[1]));
}

// ------- K1: mask + fused x -> bf16 hi/lo split (x is streamed here anyway) --------
__global__ void __launch_bounds__(256) mask_split_kernel(
    const float* __restrict__ x, const float* __restrict__ inp,
    const float* __restrict__ cmw, const float* __restrict__ thr_p,
    float* __restrict__ mask,
    __nv_bfloat16* __restrict__ xhi, __nv_bfloat16* __restrict__ xlo)
{
    __shared__ float cw[CC];
    int t = threadIdx.x;
    if (t < CC) cw[t] = cmw[t];
    __syncthreads();
    float thr = *thr_p;
    int p = blockIdx.x * 256 + t;
    int b = blockIdx.y;
    size_t off = (size_t)b * CC * HW + p;
    float acc = 0.f;
#pragma unroll 4
    for (int c = 0; c < CC; c++) {
        float xv = x[off + (size_t)c * HW];
        float d = inp[off + (size_t)c * HW] - xv;
        acc += (d > thr) ? cw[c] : 0.f;
        __nv_bfloat16 h = __float2bfloat16(xv);
        xhi[off + (size_t)c * HW] = h;
        xlo[off + (size_t)c * HW] = __float2bfloat16(xv - __bfloat162float(h));
    }
    mask[(size_t)b * HW + p] = acc;
}

// ---------------- convert W [576][192] f32 -> bf16 hi/lo ----------------
__global__ void __launch_bounds__(192) convw_kernel(
    const float* __restrict__ W, __nv_bfloat16* __restrict__ whi,
    __nv_bfloat16* __restrict__ wlo)
{
    int i = blockIdx.x * 192 + threadIdx.x;
    float v = W[i];
    __nv_bfloat16 h = __float2bfloat16(v);
    whi[i] = h;
    wlo[i] = __float2bfloat16(v - __bfloat162float(h));
}

// ------------- HMMA bf16-split GEMM: C[M,16384] = A[M,192] @ B[192,16384] -----------
// CTA: M=64, N=128, 8 warps (warp tile 32x32). A resident; B double-buffered k32.
// 3 passes hi*hi + hi*lo + lo*hi; TWO accumulator sets to break HMMA dep chains.
__global__ void __launch_bounds__(256, 2) gemm_hmma(
    const __nv_bfloat16* __restrict__ Ahi, const __nv_bfloat16* __restrict__ Alo,
    size_t sA,
    const __nv_bfloat16* __restrict__ Bhi, const __nv_bfloat16* __restrict__ Blo,
    size_t sB, float* __restrict__ C, size_t sC)
{
    extern __shared__ __nv_bfloat16 sm[];
    __nv_bfloat16* As = sm;                    // [2 half][64][200]
    __nv_bfloat16* Bs = sm + 2 * AS_HALF;      // [2 buf][2 half][32][136]
    const int N = HW;
    int b = blockIdx.z;
    Ahi += (size_t)b * sA; Alo += (size_t)b * sA;
    Bhi += (size_t)b * sB; Blo += (size_t)b * sB;
    C   += (size_t)b * sC;
    int n0 = blockIdx.x * 128, m0 = blockIdx.y * 64;
    int tid = threadIdx.x, lane = tid & 31, w = tid >> 5;
    int wm = (w & 1) * 32;          // 2 warps along M
    int wn = (w >> 1) * 32;         // 4 warps along N
    uint32_t sAu = smem_u32(As), sBu = smem_u32(Bs);

    // ---- prefetch B chunk 0 (group 0) ----
#pragma unroll
    for (int i = 0; i < 4; i++) {
        int idx = tid + i * 256;               // 0..1023
        int half = idx >> 9, r = (idx >> 4) & 31, seg = idx & 15;
        const __nv_bfloat16* src =
            (half ? Blo : Bhi) + (size_t)r * N + n0 + seg * 8;
        cp16(sBu + 2 * (half * BS_HALF + r * 136 + seg * 8), src);
    }
    asm volatile("cp.async.commit_group;" ::: "memory");
    // ---- stage A (group 1) ----
#pragma unroll
    for (int i = 0; i < 12; i++) {
        int idx = tid + i * 256;               // 0..3071
        int half = idx >= 1536;
        int r = (idx - half * 1536) / 24;
        int seg = idx % 24;
        const __nv_bfloat16* src =
            (half ? Alo : Ahi) + (size_t)(m0 + r) * GK + seg * 8;
        cp16(sAu + 2 * (half * AS_HALF + r * 200 + seg * 8), src);
    }
    asm volatile("cp.async.commit_group;" ::: "memory");

    float acc0[2][4][4], acc1[2][4][4];
#pragma unroll
    for (int i = 0; i < 2; i++)
#pragma unroll
        for (int j = 0; j < 4; j++)
#pragma unroll
            for (int q = 0; q < 4; q++) { acc0[i][j][q] = 0.f; acc1[i][j][q] = 0.f; }

    int a_lr = (lane & 15), a_kh = (lane >> 4) << 3;

    for (int kt = 0; kt < 6; kt++) {
        int buf = kt & 1;
        if (kt < 5) {
#pragma unroll
            for (int i = 0; i < 4; i++) {
                int idx = tid + i * 256;
                int half = idx >> 9, r = (idx >> 4) & 31, seg = idx & 15;
                const __nv_bfloat16* src = (half ? Blo : Bhi)
                    + (size_t)((kt + 1) * 32 + r) * N + n0 + seg * 8;
                cp16(sBu + 2 * ((buf ^ 1) * BS_BUF + half * BS_HALF
                                + r * 136 + seg * 8), src);
            }
            asm volatile("cp.async.commit_group;" ::: "memory");
            asm volatile("cp.async.wait_group 1;" ::: "memory");
        } else {
            asm volatile("cp.async.wait_group 0;" ::: "memory");
        }
        __syncthreads();
#pragma unroll
        for (int ks = 0; ks < 2; ks++) {
            int k0 = kt * 32 + ks * 16;
            uint32_t Ah[2][4], Al[2][4], Bh[2][4], Bl[2][4];
#pragma unroll
            for (int mt = 0; mt < 2; mt++) {
                uint32_t addr = sAu + 2 * ((wm + mt * 16 + a_lr) * 200 + k0 + a_kh);
                ldsm4(Ah[mt], addr);
                ldsm4(Al[mt], addr + 2 * AS_HALF);
            }
#pragma unroll
            for (int j = 0; j < 2; j++) {
                uint32_t addr = sBu + 2 * (buf * BS_BUF
                    + (ks * 16 + a_lr) * 136 + wn + j * 16 + a_kh);
                ldsm4t(Bh[j], addr);
                ldsm4t(Bl[j], addr + 2 * BS_HALF);
            }
            // group 1: 8 independent hh -> acc0
#pragma unroll
            for (int mt = 0; mt < 2; mt++)
#pragma unroll
                for (int j = 0; j < 2; j++)
#pragma unroll
                    for (int hn = 0; hn < 2; hn++)
                        mma16816(acc0[mt][j * 2 + hn], Ah[mt], &Bh[j][hn * 2]);
            // group 2: 8 independent hl -> acc1
#pragma unroll
            for (int mt = 0; mt < 2; mt++)
#pragma unroll
                for (int j = 0; j < 2; j++)
#pragma unroll
                    for (int hn = 0; hn < 2; hn++)
                        mma16816(acc1[mt][j * 2 + hn], Ah[mt], &Bl[j][hn * 2]);
            // group 3: 8 lh -> acc1 (reuse distance 8)
#pragma unroll
            for (int mt = 0; mt < 2; mt++)
#pragma unroll
                for (int j = 0; j < 2; j++)
#pragma unroll
                    for (int hn = 0; hn < 2; hn++)
                        mma16816(acc1[mt][j * 2 + hn], Al[mt], &Bh[j][hn * 2]);
        }
        __syncthreads();
    }

    int g = lane >> 2, tg = lane & 3;
#pragma unroll
    for (int mt = 0; mt < 2; mt++) {
        int row = m0 + wm + mt * 16 + g;
#pragma unroll
        for (int nt = 0; nt < 4; nt++) {
            int col = n0 + wn + nt * 8 + tg * 2;
            float* c0 = acc0[mt][nt];
            float* c1 = acc1[mt][nt];
            *(float2*)&C[(size_t)row * N + col] =
                make_float2(c0[0] + c1[0], c0[1] + c1[1]);
            *(float2*)&C[(size_t)(row + 8) * N + col] =
                make_float2(c0[2] + c1[2], c0[3] + c1[3]);
        }
    }
}

// ------- K3: depthwise 3x3, 4 rows/thread; q,k -> f32(+mask+sumsq), v -> bf16 -------
__global__ void __launch_bounds__(128) dw_kernel(
    const float* __restrict__ in, const float* __restrict__ dww,
    const float* __restrict__ mask, float* __restrict__ out,
    float* __restrict__ ssp,
    __nv_bfloat16* __restrict__ vhi, __nv_bfloat16* __restrict__ vlo)
{
    int xx = threadIdx.x;
    int y0 = blockIdx.x * 4;
    int oc = blockIdx.y, b = blockIdx.z;
    size_t base = ((size_t)b * C3 + oc) * HW;
    float w[9];
#pragma unroll
    for (int i = 0; i < 9; i++) w[i] = __ldg(&dww[oc * 9 + i]);
    float cl[6], cm[6], cr[6];
#pragma unroll
    for (int i = 0; i < 6; i++) {
        int yy = y0 - 1 + i;
        bool vy = (yy >= 0) && (yy < HH);
        const float* rp = in + base + (size_t)yy * WW;
        cm[i] = vy ? rp[xx] : 0.f;
        cl[i] = (vy && xx > 0)      ? rp[xx - 1] : 0.f;
        cr[i] = (vy && xx < WW - 1) ? rp[xx + 1] : 0.f;
    }
    float acc[4];
#pragma unroll
    for (int r = 0; r < 4; r++) {
        float a = 0.f;
#pragma unroll
        for (int j = 0; j < 3; j++)
            a += cl[r+j]*w[j*3] + cm[r+j]*w[j*3+1] + cr[r+j]*w[j*3+2];
        acc[r] = a;
    }
    if (oc < 2 * CC) {          // q or k: apply mask, f32 out, sumsq partials
        float ss = 0.f;
#pragma unroll
        for (int r = 0; r < 4; r++) {
            float mv = mask[(size_t)b * HW + (y0 + r) * WW + xx];
            acc[r] *= mv;
            ss += acc[r] * acc[r];
        }
#pragma unroll
        for (int o = 16; o; o >>= 1) ss += __shfl_down_sync(0xffffffffu, ss, o);
        __shared__ float red[4];
        if ((xx & 31) == 0) red[xx >> 5] = ss;
        __syncthreads();
        if (xx == 0)
            ssp[(size_t)(b * 2 * CC + oc) * 32 + blockIdx.x] =
                red[0] + red[1] + red[2] + red[3];
        size_t ob = ((size_t)b * 2 * CC + oc) * HW;
#pragma unroll
        for (int r = 0; r < 4; r++)
            out[ob + (size_t)(y0 + r) * WW + xx] = acc[r];
    } else {                    // v: write split bf16 directly
        size_t vb = ((size_t)b * GK + (oc - 2 * CC)) * HW;
#pragma unroll
        for (int r = 0; r < 4; r++) {
            __nv_bfloat16 h = __float2bfloat16(acc[r]);
            vhi[vb + (size_t)(y0 + r) * WW + xx] = h;
            vlo[vb + (size_t)(y0 + r) * WW + xx] =
                __float2bfloat16(acc[r] - __bfloat162float(h));
        }
    }
}

// ---------------- K3b: sumsq reduce ----------------
__global__ void __launch_bounds__(32) ssreduce_kernel(
    const float* __restrict__ part, float* __restrict__ sumsq)
{
    int id = blockIdx.x, t = threadIdx.x;
    float v = part[(size_t)id * 32 + t];
#pragma unroll
    for (int o = 16; o; o >>= 1) v += __shfl_down_sync(0xffffffffu, v, o);
    if (t == 0) sumsq[id] = v;
}

// ---------------- K4: QK^T partials (f32x2) ----------------
__global__ void __launch_bounds__(64) qk_kernel(
    const float* __restrict__ qk, float* __restrict__ Spart)
{
    int chunk = blockIdx.x, h = blockIdx.y, b = blockIdx.z;
    const float* qbase = qk + ((size_t)b * 2 * CC + h * CH) * HW;
    const float* kbase = qk + ((size_t)b * 2 * CC + CC + h * CH) * HW;
    int p0 = chunk * 512;
    __shared__ float qs[CH][34];
    __shared__ float ks[CH][34];
    int t = threadIdx.x, ti = t >> 3, tj = t & 7;
    unsigned long long acc[6][6];
#pragma unroll
    for (int i = 0; i < 6; i++)
#pragma unroll
        for (int j = 0; j < 6; j++) acc[i][j] = 0ULL;
    for (int sub = 0; sub < 16; sub++) {
        int pp = p0 + sub * 32;
        __syncthreads();
#pragma unroll
        for (int j = 0; j < 6; j++) {
            int id = t + j * 64;
            int row = id >> 3, c4 = (id & 7) * 4;
            float4 v = *(const float4*)(qbase + (size_t)row * HW + pp + c4);
            qs[row][c4] = v.x; qs[row][c4+1] = v.y;
            qs[row][c4+2] = v.z; qs[row][c4+3] = v.w;
            float4 w = *(const float4*)(kbase + (size_t)row * HW + pp + c4);
            ks[row][c4] = w.x; ks[row][c4+1] = w.y;
            ks[row][c4+2] = w.z; ks[row][c4+3] = w.w;
        }
        __syncthreads();
#pragma unroll
        for (int kk = 0; kk < 16; kk++) {
            unsigned long long q2[6], k2[6];
#pragma unroll
            for (int i = 0; i < 6; i++)
                q2[i] = *(const unsigned long long*)&qs[ti * 6 + i][kk * 2];
#pragma unroll
            for (int j = 0; j < 6; j++)
                k2[j] = *(const unsigned long long*)&ks[tj * 6 + j][kk * 2];
#pragma unroll
            for (int i = 0; i < 6; i++)
#pragma unroll
                for (int j = 0; j < 6; j++)
                    acc[i][j] = fma2(q2[i], k2[j], acc[i][j]);
        }
    }
    float* Sp = Spart + (size_t)chunk * (BB * NHEADS * CH * CH)
                      + (size_t)(b * NHEADS + h) * (CH * CH);
#pragma unroll
    for (int i = 0; i < 6; i++)
#pragma unroll
        for (int j = 0; j < 6; j++) {
            float2 f = unpack2(acc[i][j]);
            Sp[(ti * 6 + i) * CH + tj * 6 + j] = f.x + f.y;
        }
}

// ------ K5: reduce S + cosine scale + softmax + fold proj -> M (bf16 hi/lo) --------
__global__ void __launch_bounds__(256) attn_kernel(
    const float* __restrict__ Spart, const float* __restrict__ sumsq,
    const float* __restrict__ temp, const float* __restrict__ projw,
    __nv_bfloat16* __restrict__ Mhi, __nv_bfloat16* __restrict__ Mlo)
{
    int h = blockIdx.x, b = blockIdx.y;
    __shared__ float att[CH][CH];
    __shared__ float rnq[CH], rnk[CH];
    int t = threadIdx.x;
    if (t < CH) {
        float nq = sqrtf(sumsq[b * 2 * CC + h * CH + t]);
        float nk = sqrtf(sumsq[b * 2 * CC + CC + h * CH + t]);
        rnq[t] = 1.f / fmaxf(nq, 1e-12f);
        rnk[t] = 1.f / fmaxf(nk, 1e-12f);
    }
    __syncthreads();
    float T = temp[h];
    size_t sp0 = (size_t)(b * NHEADS + h) * (CH * CH);
    for (int i = t; i < CH * CH; i += 256) {
        float s = 0.f;
#pragma unroll
        for (int c = 0; c < 32; c++)
            s += Spart[(size_t)c * (BB * NHEADS * CH * CH) + sp0 + i];
        int cR = i / CH, d = i % CH;
        att[cR][d] = s * rnq[cR] * rnk[d] * T;
    }
    __syncthreads();
    if (t < CH) {
        float mx = -1e30f;
#pragma unroll
        for (int d = 0; d < CH; d++) mx = fmaxf(mx, att[t][d]);
        float sum = 0.f;
#pragma unroll
        for (int d = 0; d < CH; d++) {
            float e = expf(att[t][d] - mx);
            att[t][d] = e;
            sum += e;
        }
        float inv = 1.f / sum;
#pragma unroll
        for (int d = 0; d < CH; d++) att[t][d] *= inv;
    }
    __syncthreads();
    for (int i = t; i < CC * CH; i += 256) {
        int o = i / CH, d = i % CH;
        float s = 0.f;
#pragma unroll
        for (int c = 0; c < CH; c++)
            s += projw[o * CC + h * CH + c] * att[c][d];
        size_t idx = ((size_t)b * CC + o) * CC + h * CH + d;
        __nv_bfloat16 hi = __float2bfloat16(s);
        Mhi[idx] = hi;
        Mlo[idx] = __float2bfloat16(s - __bfloat162float(hi));
    }
}

// ---------------- launch ----------------
extern "C" void kernel_launch(void* const* d_in, const int* in_sizes, int n_in,
                              void* d_out, int out_size)
{
    const float* x     = (const float*)d_in[0];
    const float* inp   = (const float*)d_in[1];
    const float* qkvw  = (const float*)d_in[2];
    const float* dww   = (const float*)d_in[3];
    const float* projw = (const float*)d_in[4];
    const float* cmw   = (const float*)d_in[5];
    const float* temp  = (const float*)d_in[6];
    const float* thr   = (const float*)d_in[7];
    float* out = (float*)d_out;

    float *p_mask, *p_qkv, *p_qkvd, *p_ssp, *p_sumsq, *p_spart;
    __nv_bfloat16 *p_whi, *p_wlo, *p_xhi, *p_xlo, *p_vhi, *p_vlo, *p_mhi, *p_mlo;
    cudaGetSymbolAddress((void**)&p_mask,  g_mask);
    cudaGetSymbolAddress((void**)&p_qkv,   g_qkv);
    cudaGetSymbolAddress((void**)&p_qkvd,  g_qkvd);
    cudaGetSymbolAddress((void**)&p_ssp,   g_ssp);
    cudaGetSymbolAddress((void**)&p_sumsq, g_sumsq);
    cudaGetSymbolAddress((void**)&p_spart, g_Spart);
    cudaGetSymbolAddress((void**)&p_whi,   g_Whi);
    cudaGetSymbolAddress((void**)&p_wlo,   g_Wlo);
    cudaGetSymbolAddress((void**)&p_xhi,   g_xhi);
    cudaGetSymbolAddress((void**)&p_xlo,   g_xlo);
    cudaGetSymbolAddress((void**)&p_vhi,   g_vhi);
    cudaGetSymbolAddress((void**)&p_vlo,   g_vlo);
    cudaGetSymbolAddress((void**)&p_mhi,   g_Mhi);
    cudaGetSymbolAddress((void**)&p_mlo,   g_Mlo);

    cudaFuncSetAttribute(gemm_hmma,
        cudaFuncAttributeMaxDynamicSharedMemorySize, GEMM_SMEM);

    // K1: mask + x bf16 split (fused)
    mask_split_kernel<<<dim3(HW / 256, BB), 256>>>(x, inp, cmw, thr, p_mask,
                                                   p_xhi, p_xlo);
    // convert W
    convw_kernel<<<C3, 192>>>(qkvw, p_whi, p_wlo);
    // K2: qkv = W @ x  (tensor cores, bf16 split x3, dual accumulators)
    gemm_hmma<<<dim3(HW / 128, C3 / 64, BB), 256, GEMM_SMEM>>>(
        p_whi, p_wlo, (size_t)0, p_xhi, p_xlo, (size_t)GK * HW,
        p_qkv, (size_t)C3 * HW);
    // K3: depthwise 3x3; q,k -> f32 + mask + sumsq; v -> bf16 hi/lo
    dw_kernel<<<dim3(HH / 4, C3, BB), 128>>>(p_qkv, dww, p_mask, p_qkvd, p_ssp,
                                             p_vhi, p_vlo);
    ssreduce_kernel<<<BB * 2 * CC, 32>>>(p_ssp, p_sumsq);
    // K4: S partials
    qk_kernel<<<dim3(32, NHEADS, BB), 64>>>(p_qkvd, p_spart);
    // K5: softmax + fold proj -> bf16 hi/lo M
    attn_kernel<<<dim3(NHEADS, BB), 256>>>(p_spart, p_sumsq, temp, projw,
                                           p_mhi, p_mlo);
    // K6: out = M @ v  (tensor cores)
    gemm_hmma<<<dim3(HW / 128, CC / 64, BB), 256, GEMM_SMEM>>>(
        p_mhi, p_mlo, (size_t)CC * CC, p_vhi, p_vlo, (size_t)GK * HW,
        out, (size_t)CC * HW);
}

// round 17
// speedup vs baseline: 1.0550x; 1.0015x over previous
#include <cuda_runtime.h>
#include <cuda_bf16.h>
#include <cstdint>
#include <cstddef>

#define HH 128
#define WW 128
#define HW 16384
#define CC 192
#define C3 576
#define BB 8
#define NHEADS 4
#define CH 48
#define GK 192

// gemm tiling
#define AS_HALF (64 * 200)          // A smem elems per half (64 rows, 192+8 pad)
#define BS_HALF (32 * 136)          // B smem elems per half per buf (32 rows, 128+8 pad)
#define BS_BUF  (2 * BS_HALF)
#define GEMM_SMEM ((2 * AS_HALF + 2 * BS_BUF) * 2)   // 86016 bytes

// ---------------- scratch (static device globals) ----------------
__device__ float g_mask[BB * HW];
__device__ float g_qkv [(size_t)BB * C3 * HW];
__device__ float g_qkvd[(size_t)BB * 2 * CC * HW];   // only q,k kept in f32
__device__ float g_ssp [BB * 2 * CC * 32];
__device__ float g_sumsq[BB * 2 * CC];
__device__ float g_Spart[(size_t)32 * BB * NHEADS * CH * CH];
__device__ __nv_bfloat16 g_Whi[C3 * GK];
__device__ __nv_bfloat16 g_Wlo[C3 * GK];
__device__ __nv_bfloat16 g_xhi[(size_t)BB * GK * HW];
__device__ __nv_bfloat16 g_xlo[(size_t)BB * GK * HW];
__device__ __nv_bfloat16 g_vhi[(size_t)BB * GK * HW];
__device__ __nv_bfloat16 g_vlo[(size_t)BB * GK * HW];
__device__ __nv_bfloat16 g_Mhi[BB * CC * CC];
__device__ __nv_bfloat16 g_Mlo[BB * CC * CC];

// ---------------- helpers ----------------
__device__ __forceinline__ unsigned long long fma2(unsigned long long a,
                                                   unsigned long long b,
                                                   unsigned long long c) {
    unsigned long long d;
    asm("fma.rn.f32x2 %0, %1, %2, %3;" : "=l"(d) : "l"(a), "l"(b), "l"(c));
    return d;
}
__device__ __forceinline__ float2 unpack2(unsigned long long v) {
    float2 r;
    asm("mov.b64 {%0, %1}, %2;" : "=f"(r.x), "=f"(r.y) : "l"(v));
    return r;
}
__device__ __forceinline__ uint32_t smem_u32(const void* p) {
    uint32_t a;
    asm("{ .reg .u64 t; cvta.to.shared.u64 t, %1; cvt.u32.u64 %0, t; }"
        : "=r"(a) : "l"(p));
    return a;
}
__device__ __forceinline__ void cp16(uint32_t dst, const void* src) {
    asm volatile("cp.async.cg.shared.global [%0], [%1], 16;"
                 :: "r"(dst), "l"(src));
}
__device__ __forceinline__ void ldsm4(uint32_t* r, uint32_t a) {
    asm volatile("ldmatrix.sync.aligned.m8n8.x4.shared.b16 {%0,%1,%2,%3}, [%4];"
        : "=r"(r[0]), "=r"(r[1]), "=r"(r[2]), "=r"(r[3]) : "r"(a));
}
__device__ __forceinline__ void ldsm4t(uint32_t* r, uint32_t a) {
    asm volatile("ldmatrix.sync.aligned.m8n8.x4.trans.shared.b16 {%0,%1,%2,%3}, [%4];"
        : "=r"(r[0]), "=r"(r[1]), "=r"(r[2]), "=r"(r[3]) : "r"(a));
}
__device__ __forceinline__ void mma16816(float* c, const uint32_t* a,
                                         const uint32_t* b) {
    asm volatile(
        "mma.sync.aligned.m16n8k16.row.col.f32.bf16.bf16.f32 "
        "{%0,%1,%2,%3}, {%4,%5,%6,%7}, {%8,%9}, {%0,%1,%2,%3};"
        : "+f"(c[0]), "+f"(c[1]), "+f"(c[2]), "+f"(c[3])
        : "r"(a[0]), "r"(a[1]), "r"(a[2]), "r"(a[3]), "r"(b[0]), "r"(b[1]));
}

// ------- K1: mask + fused x -> bf16 hi/lo split (x is streamed here anyway) --------
__global__ void __launch_bounds__(256) mask_split_kernel(
    const float* __restrict__ x, const float* __restrict__ inp,
    const float* __restrict__ cmw, const float* __restrict__ thr_p,
    float* __restrict__ mask,
    __nv_bfloat16* __restrict__ xhi, __nv_bfloat16* __restrict__ xlo)
{
    __shared__ float cw[CC];
    int t = threadIdx.x;
    if (t < CC) cw[t] = cmw[t];
    __syncthreads();
    float thr = *thr_p;
    int p = blockIdx.x * 256 + t;
    int b = blockIdx.y;
    size_t off = (size_t)b * CC * HW + p;
    float acc = 0.f;
#pragma unroll 4
    for (int c = 0; c < CC; c++) {
        float xv = x[off + (size_t)c * HW];
        float d = inp[off + (size_t)c * HW] - xv;
        acc += (d > thr) ? cw[c] : 0.f;
        __nv_bfloat16 h = __float2bfloat16(xv);
        xhi[off + (size_t)c * HW] = h;
        xlo[off + (size_t)c * HW] = __float2bfloat16(xv - __bfloat162float(h));
    }
    mask[(size_t)b * HW + p] = acc;
}

// ---------------- convert W [576][192] f32 -> bf16 hi/lo ----------------
__global__ void __launch_bounds__(192) convw_kernel(
    const float* __restrict__ W, __nv_bfloat16* __restrict__ whi,
    __nv_bfloat16* __restrict__ wlo)
{
    int i = blockIdx.x * 192 + threadIdx.x;
    float v = W[i];
    __nv_bfloat16 h = __float2bfloat16(v);
    whi[i] = h;
    wlo[i] = __float2bfloat16(v - __bfloat162float(h));
}

// ------------- HMMA bf16-split GEMM: C[M,16384] = A[M,192] @ B[192,16384] -----------
// CTA: M=64, N=128, 8 warps (warp tile 32x32). A resident; B double-buffered k32.
// 3 passes hi*hi + hi*lo + lo*hi; TWO accumulator sets to break HMMA dep chains.
__global__ void __launch_bounds__(256, 2) gemm_hmma(
    const __nv_bfloat16* __restrict__ Ahi, const __nv_bfloat16* __restrict__ Alo,
    size_t sA,
    const __nv_bfloat16* __restrict__ Bhi, const __nv_bfloat16* __restrict__ Blo,
    size_t sB, float* __restrict__ C, size_t sC)
{
    extern __shared__ __nv_bfloat16 sm[];
    __nv_bfloat16* As = sm;                    // [2 half][64][200]
    __nv_bfloat16* Bs = sm + 2 * AS_HALF;      // [2 buf][2 half][32][136]
    const int N = HW;
    int b = blockIdx.z;
    Ahi += (size_t)b * sA; Alo += (size_t)b * sA;
    Bhi += (size_t)b * sB; Blo += (size_t)b * sB;
    C   += (size_t)b * sC;
    int n0 = blockIdx.x * 128, m0 = blockIdx.y * 64;
    int tid = threadIdx.x, lane = tid & 31, w = tid >> 5;
    int wm = (w & 1) * 32;          // 2 warps along M
    int wn = (w >> 1) * 32;         // 4 warps along N
    uint32_t sAu = smem_u32(As), sBu = smem_u32(Bs);

    // ---- prefetch B chunk 0 (group 0) ----
#pragma unroll
    for (int i = 0; i < 4; i++) {
        int idx = tid + i * 256;               // 0..1023
        int half = idx >> 9, r = (idx >> 4) & 31, seg = idx & 15;
        const __nv_bfloat16* src =
            (half ? Blo : Bhi) + (size_t)r * N + n0 + seg * 8;
        cp16(sBu + 2 * (half * BS_HALF + r * 136 + seg * 8), src);
    }
    asm volatile("cp.async.commit_group;" ::: "memory");
    // ---- stage A (group 1) ----
#pragma unroll
    for (int i = 0; i < 12; i++) {
        int idx = tid + i * 256;               // 0..3071
        int half = idx >= 1536;
        int r = (idx - half * 1536) / 24;
        int seg = idx % 24;
        const __nv_bfloat16* src =
            (half ? Alo : Ahi) + (size_t)(m0 + r) * GK + seg * 8;
        cp16(sAu + 2 * (half * AS_HALF + r * 200 + seg * 8), src);
    }
    asm volatile("cp.async.commit_group;" ::: "memory");

    float acc0[2][4][4], acc1[2][4][4];
#pragma unroll
    for (int i = 0; i < 2; i++)
#pragma unroll
        for (int j = 0; j < 4; j++)
#pragma unroll
            for (int q = 0; q < 4; q++) { acc0[i][j][q] = 0.f; acc1[i][j][q] = 0.f; }

    int a_lr = (lane & 15), a_kh = (lane >> 4) << 3;

    for (int kt = 0; kt < 6; kt++) {
        int buf = kt & 1;
        if (kt < 5) {
#pragma unroll
            for (int i = 0; i < 4; i++) {
                int idx = tid + i * 256;
                int half = idx >> 9, r = (idx >> 4) & 31, seg = idx & 15;
                const __nv_bfloat16* src = (half ? Blo : Bhi)
                    + (size_t)((kt + 1) * 32 + r) * N + n0 + seg * 8;
                cp16(sBu + 2 * ((buf ^ 1) * BS_BUF + half * BS_HALF
                                + r * 136 + seg * 8), src);
            }
            asm volatile("cp.async.commit_group;" ::: "memory");
            asm volatile("cp.async.wait_group 1;" ::: "memory");
        } else {
            asm volatile("cp.async.wait_group 0;" ::: "memory");
        }
        __syncthreads();
#pragma unroll
        for (int ks = 0; ks < 2; ks++) {
            int k0 = kt * 32 + ks * 16;
            uint32_t Ah[2][4], Al[2][4], Bh[2][4], Bl[2][4];
#pragma unroll
            for (int mt = 0; mt < 2; mt++) {
                uint32_t addr = sAu + 2 * ((wm + mt * 16 + a_lr) * 200 + k0 + a_kh);
                ldsm4(Ah[mt], addr);
                ldsm4(Al[mt], addr + 2 * AS_HALF);
            }
#pragma unroll
            for (int j = 0; j < 2; j++) {
                uint32_t addr = sBu + 2 * (buf * BS_BUF
                    + (ks * 16 + a_lr) * 136 + wn + j * 16 + a_kh);
                ldsm4t(Bh[j], addr);
                ldsm4t(Bl[j], addr + 2 * BS_HALF);
            }
            // group 1: 8 independent hh -> acc0
#pragma unroll
            for (int mt = 0; mt < 2; mt++)
#pragma unroll
                for (int j = 0; j < 2; j++)
#pragma unroll
                    for (int hn = 0; hn < 2; hn++)
                        mma16816(acc0[mt][j * 2 + hn], Ah[mt], &Bh[j][hn * 2]);
            // group 2: 8 independent hl -> acc1
#pragma unroll
            for (int mt = 0; mt < 2; mt++)
#pragma unroll
                for (int j = 0; j < 2; j++)
#pragma unroll
                    for (int hn = 0; hn < 2; hn++)
                        mma16816(acc1[mt][j * 2 + hn], Ah[mt], &Bl[j][hn * 2]);
            // group 3: 8 lh -> acc1 (reuse distance 8)
#pragma unroll
            for (int mt = 0; mt < 2; mt++)
#pragma unroll
                for (int j = 0; j < 2; j++)
#pragma unroll
                    for (int hn = 0; hn < 2; hn++)
                        mma16816(acc1[mt][j * 2 + hn], Al[mt], &Bh[j][hn * 2]);
        }
        __syncthreads();
    }

    int g = lane >> 2, tg = lane & 3;
#pragma unroll
    for (int mt = 0; mt < 2; mt++) {
        int row = m0 + wm + mt * 16 + g;
#pragma unroll
        for (int nt = 0; nt < 4; nt++) {
            int col = n0 + wn + nt * 8 + tg * 2;
            float* c0 = acc0[mt][nt];
            float* c1 = acc1[mt][nt];
            *(float2*)&C[(size_t)row * N + col] =
                make_float2(c0[0] + c1[0], c0[1] + c1[1]);
            *(float2*)&C[(size_t)(row + 8) * N + col] =
                make_float2(c0[2] + c1[2], c0[3] + c1[3]);
        }
    }
}

// ------- K3: depthwise 3x3, 4 rows/thread; q,k -> f32(+mask+sumsq), v -> bf16 -------
__global__ void __launch_bounds__(128) dw_kernel(
    const float* __restrict__ in, const float* __restrict__ dww,
    const float* __restrict__ mask, float* __restrict__ out,
    float* __restrict__ ssp,
    __nv_bfloat16* __restrict__ vhi, __nv_bfloat16* __restrict__ vlo)
{
    int xx = threadIdx.x;
    int y0 = blockIdx.x * 4;
    int oc = blockIdx.y, b = blockIdx.z;
    size_t base = ((size_t)b * C3 + oc) * HW;
    float w[9];
#pragma unroll
    for (int i = 0; i < 9; i++) w[i] = __ldg(&dww[oc * 9 + i]);
    float cl[6], cm[6], cr[6];
#pragma unroll
    for (int i = 0; i < 6; i++) {
        int yy = y0 - 1 + i;
        bool vy = (yy >= 0) && (yy < HH);
        const float* rp = in + base + (size_t)yy * WW;
        cm[i] = vy ? rp[xx] : 0.f;
        cl[i] = (vy && xx > 0)      ? rp[xx - 1] : 0.f;
        cr[i] = (vy && xx < WW - 1) ? rp[xx + 1] : 0.f;
    }
    float acc[4];
#pragma unroll
    for (int r = 0; r < 4; r++) {
        float a = 0.f;
#pragma unroll
        for (int j = 0; j < 3; j++)
            a += cl[r+j]*w[j*3] + cm[r+j]*w[j*3+1] + cr[r+j]*w[j*3+2];
        acc[r] = a;
    }
    if (oc < 2 * CC) {          // q or k: apply mask, f32 out, sumsq partials
        float ss = 0.f;
#pragma unroll
        for (int r = 0; r < 4; r++) {
            float mv = mask[(size_t)b * HW + (y0 + r) * WW + xx];
            acc[r] *= mv;
            ss += acc[r] * acc[r];
        }
#pragma unroll
        for (int o = 16; o; o >>= 1) ss += __shfl_down_sync(0xffffffffu, ss, o);
        __shared__ float red[4];
        if ((xx & 31) == 0) red[xx >> 5] = ss;
        __syncthreads();
        if (xx == 0)
            ssp[(size_t)(b * 2 * CC + oc) * 32 + blockIdx.x] =
                red[0] + red[1] + red[2] + red[3];
        size_t ob = ((size_t)b * 2 * CC + oc) * HW;
#pragma unroll
        for (int r = 0; r < 4; r++)
            out[ob + (size_t)(y0 + r) * WW + xx] = acc[r];
    } else {                    // v: write split bf16 directly
        size_t vb = ((size_t)b * GK + (oc - 2 * CC)) * HW;
#pragma unroll
        for (int r = 0; r < 4; r++) {
            __nv_bfloat16 h = __float2bfloat16(acc[r]);
            vhi[vb + (size_t)(y0 + r) * WW + xx] = h;
            vlo[vb + (size_t)(y0 + r) * WW + xx] =
                __float2bfloat16(acc[r] - __bfloat162float(h));
        }
    }
}

// ---------------- K3b: sumsq reduce ----------------
__global__ void __launch_bounds__(32) ssreduce_kernel(
    const float* __restrict__ part, float* __restrict__ sumsq)
{
    int id = blockIdx.x, t = threadIdx.x;
    float v = part[(size_t)id * 32 + t];
#pragma unroll
    for (int o = 16; o; o >>= 1) v += __shfl_down_sync(0xffffffffu, v, o);
    if (t == 0) sumsq[id] = v;
}

// ---------------- K4: QK^T partials (f32x2) ----------------
__global__ void __launch_bounds__(64) qk_kernel(
    const float* __restrict__ qk, float* __restrict__ Spart)
{
    int chunk = blockIdx.x, h = blockIdx.y, b = blockIdx.z;
    const float* qbase = qk + ((size_t)b * 2 * CC + h * CH) * HW;
    const float* kbase = qk + ((size_t)b * 2 * CC + CC + h * CH) * HW;
    int p0 = chunk * 512;
    __shared__ float qs[CH][34];
    __shared__ float ks[CH][34];
    int t = threadIdx.x, ti = t >> 3, tj = t & 7;
    unsigned long long acc[6][6];
#pragma unroll
    for (int i = 0; i < 6; i++)
#pragma unroll
        for (int j = 0; j < 6; j++) acc[i][j] = 0ULL;
    for (int sub = 0; sub < 16; sub++) {
        int pp = p0 + sub * 32;
        __syncthreads();
#pragma unroll
        for (int j = 0; j < 6; j++) {
            int id = t + j * 64;
            int row = id >> 3, c4 = (id & 7) * 4;
            float4 v = *(const float4*)(qbase + (size_t)row * HW + pp + c4);
            qs[row][c4] = v.x; qs[row][c4+1] = v.y;
            qs[row][c4+2] = v.z; qs[row][c4+3] = v.w;
            float4 w = *(const float4*)(kbase + (size_t)row * HW + pp + c4);
            ks[row][c4] = w.x; ks[row][c4+1] = w.y;
            ks[row][c4+2] = w.z; ks[row][c4+3] = w.w;
        }
        __syncthreads();
#pragma unroll
        for (int kk = 0; kk < 16; kk++) {
            unsigned long long q2[6], k2[6];
#pragma unroll
            for (int i = 0; i < 6; i++)
                q2[i] = *(const unsigned long long*)&qs[ti * 6 + i][kk * 2];
#pragma unroll
            for (int j = 0; j < 6; j++)
                k2[j] = *(const unsigned long long*)&ks[tj * 6 + j][kk * 2];
#pragma unroll
            for (int i = 0; i < 6; i++)
#pragma unroll
                for (int j = 0; j < 6; j++)
                    acc[i][j] = fma2(q2[i], k2[j], acc[i][j]);
        }
    }
    float* Sp = Spart + (size_t)chunk * (BB * NHEADS * CH * CH)
                      + (size_t)(b * NHEADS + h) * (CH * CH);
#pragma unroll
    for (int i = 0; i < 6; i++)
#pragma unroll
        for (int j = 0; j < 6; j++) {
            float2 f = unpack2(acc[i][j]);
            Sp[(ti * 6 + i) * CH + tj * 6 + j] = f.x + f.y;
        }
}

// ------ K5: reduce S + cosine scale + softmax + fold proj -> M (bf16 hi/lo) --------
__global__ void __launch_bounds__(256) attn_kernel(
    const float* __restrict__ Spart, const float* __restrict__ sumsq,
    const float* __restrict__ temp, const float* __restrict__ projw,
    __nv_bfloat16* __restrict__ Mhi, __nv_bfloat16* __restrict__ Mlo)
{
    int h = blockIdx.x, b = blockIdx.y;
    __shared__ float att[CH][CH];
    __shared__ float rnq[CH], rnk[CH];
    int t = threadIdx.x;
    if (t < CH) {
        float nq = sqrtf(sumsq[b * 2 * CC + h * CH + t]);
        float nk = sqrtf(sumsq[b * 2 * CC + CC + h * CH + t]);
        rnq[t] = 1.f / fmaxf(nq, 1e-12f);
        rnk[t] = 1.f / fmaxf(nk, 1e-12f);
    }
    __syncthreads();
    float T = temp[h];
    size_t sp0 = (size_t)(b * NHEADS + h) * (CH * CH);
    for (int i = t; i < CH * CH; i += 256) {
        float s = 0.f;
#pragma unroll
        for (int c = 0; c < 32; c++)
            s += Spart[(size_t)c * (BB * NHEADS * CH * CH) + sp0 + i];
        int cR = i / CH, d = i % CH;
        att[cR][d] = s * rnq[cR] * rnk[d] * T;
    }
    __syncthreads();
    if (t < CH) {
        float mx = -1e30f;
#pragma unroll
        for (int d = 0; d < CH; d++) mx = fmaxf(mx, att[t][d]);
        float sum = 0.f;
#pragma unroll
        for (int d = 0; d < CH; d++) {
            float e = expf(att[t][d] - mx);
            att[t][d] = e;
            sum += e;
        }
        float inv = 1.f / sum;
#pragma unroll
        for (int d = 0; d < CH; d++) att[t][d] *= inv;
    }
    __syncthreads();
    for (int i = t; i < CC * CH; i += 256) {
        int o = i / CH, d = i % CH;
        float s = 0.f;
#pragma unroll
        for (int c = 0; c < CH; c++)
            s += projw[o * CC + h * CH + c] * att[c][d];
        size_t idx = ((size_t)b * CC + o) * CC + h * CH + d;
        __nv_bfloat16 hi = __float2bfloat16(s);
        Mhi[idx] = hi;
        Mlo[idx] = __float2bfloat16(s - __bfloat162float(hi));
    }
}

// ---------------- launch ----------------
extern "C" void kernel_launch(void* const* d_in, const int* in_sizes, int n_in,
                              void* d_out, int out_size)
{
    const float* x     = (const float*)d_in[0];
    const float* inp   = (const float*)d_in[1];
    const float* qkvw  = (const float*)d_in[2];
    const float* dww   = (const float*)d_in[3];
    const float* projw = (const float*)d_in[4];
    const float* cmw   = (const float*)d_in[5];
    const float* temp  = (const float*)d_in[6];
    const float* thr   = (const float*)d_in[7];
    float* out = (float*)d_out;

    float *p_mask, *p_qkv, *p_qkvd, *p_ssp, *p_sumsq, *p_spart;
    __nv_bfloat16 *p_whi, *p_wlo, *p_xhi, *p_xlo, *p_vhi, *p_vlo, *p_mhi, *p_mlo;
    cudaGetSymbolAddress((void**)&p_mask,  g_mask);
    cudaGetSymbolAddress((void**)&p_qkv,   g_qkv);
    cudaGetSymbolAddress((void**)&p_qkvd,  g_qkvd);
    cudaGetSymbolAddress((void**)&p_ssp,   g_ssp);
    cudaGetSymbolAddress((void**)&p_sumsq, g_sumsq);
    cudaGetSymbolAddress((void**)&p_spart, g_Spart);
    cudaGetSymbolAddress((void**)&p_whi,   g_Whi);
    cudaGetSymbolAddress((void**)&p_wlo,   g_Wlo);
    cudaGetSymbolAddress((void**)&p_xhi,   g_xhi);
    cudaGetSymbolAddress((void**)&p_xlo,   g_xlo);
    cudaGetSymbolAddress((void**)&p_vhi,   g_vhi);
    cudaGetSymbolAddress((void**)&p_vlo,   g_vlo);
    cudaGetSymbolAddress((void**)&p_mhi,   g_Mhi);
    cudaGetSymbolAddress((void**)&p_mlo,   g_Mlo);

    cudaFuncSetAttribute(gemm_hmma,
        cudaFuncAttributeMaxDynamicSharedMemorySize, GEMM_SMEM);

    // K1: mask + x bf16 split (fused)
    mask_split_kernel<<<dim3(HW / 256, BB), 256>>>(x, inp, cmw, thr, p_mask,
                                                   p_xhi, p_xlo);
    // convert W
    convw_kernel<<<C3, 192>>>(qkvw, p_whi, p_wlo);
    // K2: qkv = W @ x  (tensor cores, bf16 split x3, dual accumulators)
    gemm_hmma<<<dim3(HW / 128, C3 / 64, BB), 256, GEMM_SMEM>>>(
        p_whi, p_wlo, (size_t)0, p_xhi, p_xlo, (size_t)GK * HW,
        p_qkv, (size_t)C3 * HW);
    // K3: depthwise 3x3; q,k -> f32 + mask + sumsq; v -> bf16 hi/lo
    dw_kernel<<<dim3(HH / 4, C3, BB), 128>>>(p_qkv, dww, p_mask, p_qkvd, p_ssp,
                                             p_vhi, p_vlo);
    ssreduce_kernel<<<BB * 2 * CC, 32>>>(p_ssp, p_sumsq);
    // K4: S partials
    qk_kernel<<<dim3(32, NHEADS, BB), 64>>>(p_qkvd, p_spart);
    // K5: softmax + fold proj -> bf16 hi/lo M
    attn_kernel<<<dim3(NHEADS, BB), 256>>>(p_spart, p_sumsq, temp, projw,
                                           p_mhi, p_mlo);
    // K6: out = M @ v  (tensor cores)
    gemm_hmma<<<dim3(HW / 128, CC / 64, BB), 256, GEMM_SMEM>>>(
        p_mhi, p_mlo, (size_t)CC * CC, p_vhi, p_vlo, (size_t)GK * HW,
        out, (size_t)CC * HW);
}